// round 7
// baseline (speedup 1.0000x reference)
#include <cuda_runtime.h>

#define NN  100000
#define EE  1200000
#define HIDN 64
#define NHD 4
#define DHD 16
#define NLY 3
#define SCAN_B 1024
#define SCAN_G ((NN + SCAN_B - 1) / SCAN_B)   // 98
#define NPB 16                                 // nodes (warps) per block
#define TPB (NPB * 32)                         // 512 threads

// ---- scratch (static device globals) ----
__device__ float g_h[NN * HIDN];        // node features between layers
__device__ float g_hw0[NN * HIDN];      // transformed features (ping)
__device__ float g_hw1[NN * HIDN];      // transformed features (pong)
__device__ float g_as0[NN * NHD], g_ad0[NN * NHD];
__device__ float g_as1[NN * NHD], g_ad1[NN * NHD];
__device__ float g_c0[NLY * NHD], g_c1[NLY * NHD];
// CSR by destination: packed (src, ea-bits)
__device__ int   g_deg[NN];
__device__ int   g_rs[NN];
__device__ int   g_cur[NN];
__device__ int2  g_cse[EE];
__device__ int   g_psum[SCAN_G];

// ---------------------------------------------------------------------------
// Edge-attn constants (edge encoder is rank-1 since EIN=1):
// a_e[e,h] = ea[e]*c1[l,h] + c0[l,h]
// ---------------------------------------------------------------------------
__global__ void k_const(const float* __restrict__ w_ee, const float* __restrict__ b_ee,
                        const float* __restrict__ w_eg, const float* __restrict__ att_e)
{
    int l = blockIdx.x, j = threadIdx.x;
    __shared__ float sU[HIDN], sV[HIDN];
    const float* W = w_eg + l * HIDN * HIDN;
    float U = 0.f, V = 0.f;
    for (int k = 0; k < HIDN; k++) {
        float wk = W[k * HIDN + j];
        U += w_ee[k] * wk;
        V += b_ee[k] * wk;
    }
    sU[j] = U; sV[j] = V;
    __syncthreads();
    if (j < NHD) {
        float c1 = 0.f, c0 = 0.f;
        for (int d = 0; d < DHD; d++) {
            float a = att_e[l * HIDN + j * DHD + d];
            c1 += sU[j * DHD + d] * a;
            c0 += sV[j * DHD + d] * a;
        }
        g_c1[l * NHD + j] = c1;
        g_c0[l * NHD + j] = c0;
    }
}

// ---------------------------------------------------------------------------
// CSR build: zero -> count -> scan -> scatter (packed int2)
// ---------------------------------------------------------------------------
__global__ void k_zero()
{
    int i = blockIdx.x * blockDim.x + threadIdx.x;
    if (i < NN) g_deg[i] = 0;
}

__global__ void k_count(const int* __restrict__ ei)
{
    int e = blockIdx.x * blockDim.x + threadIdx.x;
    if (e < EE) atomicAdd(&g_deg[ei[EE + e]], 1);
}

__global__ void k_scan1()
{
    __shared__ int s[SCAN_B];
    int t = threadIdx.x, gid = blockIdx.x * SCAN_B + t;
    int v = (gid < NN) ? g_deg[gid] : 0;
    s[t] = v;
    __syncthreads();
    #pragma unroll
    for (int off = 1; off < SCAN_B; off <<= 1) {
        int u = (t >= off) ? s[t - off] : 0;
        __syncthreads();
        s[t] += u;
        __syncthreads();
    }
    if (gid < NN) g_rs[gid] = s[t] - v;            // exclusive within block
    if (t == SCAN_B - 1) g_psum[blockIdx.x] = s[t];
}

__global__ void k_scan2()
{
    __shared__ int s[SCAN_G];
    int t = threadIdx.x;
    int v = (t < SCAN_G) ? g_psum[t] : 0;
    if (t < SCAN_G) s[t] = v;
    __syncthreads();
    for (int off = 1; off < SCAN_G; off <<= 1) {
        int u = (t >= off && t < SCAN_G) ? s[t - off] : 0;
        __syncthreads();
        if (t < SCAN_G) s[t] += u;
        __syncthreads();
    }
    if (t < SCAN_G) g_psum[t] = s[t] - v;          // exclusive
}

__global__ void k_scan3()
{
    int gid = blockIdx.x * SCAN_B + threadIdx.x;
    if (gid < NN) {
        g_rs[gid] += g_psum[blockIdx.x];
        g_cur[gid] = 0;
    }
}

__global__ void k_scatter(const int* __restrict__ ei, const float* __restrict__ ea)
{
    int e = blockIdx.x * blockDim.x + threadIdx.x;
    if (e >= EE) return;
    int dst = ei[EE + e];
    int pos = g_rs[dst] + atomicAdd(&g_cur[dst], 1);
    g_cse[pos] = make_int2(ei[e], __float_as_int(ea[e]));
}

// ---------------------------------------------------------------------------
// Fused node encoder + layer-0 transform. One warp per node.
// ---------------------------------------------------------------------------
__global__ void __launch_bounds__(TPB)
k_encode_t(const float* __restrict__ x,
           const float* __restrict__ w1, const float* __restrict__ b1,
           const float* __restrict__ w2, const float* __restrict__ b2,
           const float* __restrict__ wg0,
           const float* __restrict__ atts, const float* __restrict__ attd)
{
    __shared__ float2 w2s[HIDN * 32];
    __shared__ float2 wgs[HIDN * 32];
    __shared__ float sa[HIDN], sd[HIDN];
    int tid = threadIdx.x;
    for (int i = tid; i < HIDN * 32; i += TPB) {
        int k = i >> 5, c = i & 31;
        w2s[i] = make_float2(w2[k * HIDN + c],  w2[k * HIDN + c + 32]);
        wgs[i] = make_float2(wg0[k * HIDN + c], wg0[k * HIDN + c + 32]);
    }
    if (tid < HIDN) { sa[tid] = atts[tid]; sd[tid] = attd[tid]; }
    __syncthreads();

    int warp = tid >> 5, lane = tid & 31;
    int n = blockIdx.x * NPB + warp;
    if (n >= NN) return;

    float xv[6];
    #pragma unroll
    for (int k = 0; k < 6; k++) xv[k] = x[n * 6 + k];
    float h0 = b1[lane], h1 = b1[lane + 32];
    #pragma unroll
    for (int k = 0; k < 6; k++) {
        h0 += xv[k] * w1[k * HIDN + lane];
        h1 += xv[k] * w1[k * HIDN + lane + 32];
    }
    h0 = fmaxf(h0, 0.f); h1 = fmaxf(h1, 0.f);

    float a0 = b2[lane], a1 = b2[lane + 32];
    #pragma unroll
    for (int k = 0; k < HIDN; k++) {
        float hk = (k < 32) ? __shfl_sync(0xffffffffu, h0, k)
                            : __shfl_sync(0xffffffffu, h1, k - 32);
        float2 w = w2s[k * 32 + lane];
        a0 += hk * w.x;
        a1 += hk * w.y;
    }
    g_h[n * HIDN + lane]      = a0;
    g_h[n * HIDN + lane + 32] = a1;

    float t0 = 0.f, t1 = 0.f;
    #pragma unroll
    for (int k = 0; k < HIDN; k++) {
        float hk = (k < 32) ? __shfl_sync(0xffffffffu, a0, k)
                            : __shfl_sync(0xffffffffu, a1, k - 32);
        float2 w = wgs[k * 32 + lane];
        t0 += hk * w.x;
        t1 += hk * w.y;
    }
    g_hw0[n * HIDN + lane]      = t0;
    g_hw0[n * HIDN + lane + 32] = t1;

    float rs0 = t0 * sa[lane], rs1 = t1 * sa[lane + 32];
    float rd0 = t0 * sd[lane], rd1 = t1 * sd[lane + 32];
    #pragma unroll
    for (int o = 8; o >= 1; o >>= 1) {
        rs0 += __shfl_xor_sync(0xffffffffu, rs0, o);
        rs1 += __shfl_xor_sync(0xffffffffu, rs1, o);
        rd0 += __shfl_xor_sync(0xffffffffu, rd0, o);
        rd1 += __shfl_xor_sync(0xffffffffu, rd1, o);
    }
    if (lane == 0)  { g_as0[n*NHD+0] = rs0; g_as0[n*NHD+2] = rs1;
                      g_ad0[n*NHD+0] = rd0; g_ad0[n*NHD+2] = rd1; }
    if (lane == 16) { g_as0[n*NHD+1] = rs0; g_as0[n*NHD+3] = rs1;
                      g_ad0[n*NHD+1] = rd0; g_ad0[n*NHD+3] = rd1; }
}

// ---------------------------------------------------------------------------
// Fused GAT layer: one warp per destination node. CSR walk with fully
// unrolled 8-edge chunks (invalid slots: ex=0, src=0 -> harmless loads).
// Then normalize + bias + ELU + residual + LayerNorm + projection.
// ---------------------------------------------------------------------------
__global__ void __launch_bounds__(TPB)
k_gat(const float* __restrict__ hw_in,
      const float* __restrict__ as_in, const float* __restrict__ ad_in,
      int l,
      const float* __restrict__ b_gat,
      const float* __restrict__ lng, const float* __restrict__ lnb,
      const float* __restrict__ Wn,
      const float* __restrict__ atts, const float* __restrict__ attd,
      const float* __restrict__ bn,
      float* __restrict__ hw_out,
      float* __restrict__ as_out, float* __restrict__ ad_out,
      float* __restrict__ outp, int last)
{
    __shared__ float2 ws[HIDN * 32];
    __shared__ float sa[HIDN], sd[HIDN];
    int tid = threadIdx.x;
    for (int i = tid; i < HIDN * 32; i += TPB) {
        int k = i >> 5, c = i & 31;
        ws[i] = make_float2(Wn[k * HIDN + c], Wn[k * HIDN + c + 32]);
    }
    if (!last && tid < HIDN) { sa[tid] = atts[tid]; sd[tid] = attd[tid]; }
    __syncthreads();

    int warp = tid >> 5, lane = tid & 31;
    int n = blockIdx.x * NPB + warp;
    if (n >= NN) return;

    int hd    = lane & 3;                    // score head for this lane
    int eidx  = lane >> 2;                   // score edge slot (0..7)
    int h0sel = lane >> 4;                   // head of channel `lane` (0/1)
    float c1h = g_c1[l * NHD + hd], c0h = g_c0[l * NHD + hd];
    float adh = ad_in[n * NHD + hd];
    int base = g_rs[n], dg = g_deg[n];

    float acc0 = 0.f, acc1 = 0.f, den = 0.f;
    for (int off = 0; off < dg; off += 8) {
        bool v = (off + eidx) < dg;
        int2 se = v ? g_cse[base + off + eidx] : make_int2(0, 0);
        float s = as_in[se.x * NHD + hd] + adh
                + __int_as_float(se.y) * c1h + c0h;
        s = (s > 0.f) ? s : 0.2f * s;
        float ex = v ? __expf(s) : 0.f;
        den += ex;
        #pragma unroll
        for (int j = 0; j < 8; j++) {
            int   sj = __shfl_sync(0xffffffffu, se.x, j * 4);
            float e0 = __shfl_sync(0xffffffffu, ex, j * 4 + h0sel);
            float e1 = __shfl_sync(0xffffffffu, ex, j * 4 + 2 + h0sel);
            acc0 += e0 * hw_in[sj * HIDN + lane];
            acc1 += e1 * hw_in[sj * HIDN + lane + 32];
        }
    }
    // reduce den across edge slots (lanes sharing lane&3)
    den += __shfl_xor_sync(0xffffffffu, den, 4);
    den += __shfl_xor_sync(0xffffffffu, den, 8);
    den += __shfl_xor_sync(0xffffffffu, den, 16);
    float den0 = __shfl_sync(0xffffffffu, den, h0sel);
    float den1 = __shfl_sync(0xffffffffu, den, 2 + h0sel);

    float v0 = acc0 / (den0 + 1e-16f) + b_gat[l * HIDN + lane];
    float v1 = acc1 / (den1 + 1e-16f) + b_gat[l * HIDN + lane + 32];
    v0 = (v0 > 0.f) ? v0 : expm1f(v0);
    v1 = (v1 > 0.f) ? v1 : expm1f(v1);

    float x0 = g_h[n * HIDN + lane]      + v0;
    float x1 = g_h[n * HIDN + lane + 32] + v1;

    float s = x0 + x1;
    #pragma unroll
    for (int o = 16; o; o >>= 1) s += __shfl_xor_sync(0xffffffffu, s, o);
    float mean = s * (1.f / 64.f);
    float vv = (x0 - mean) * (x0 - mean) + (x1 - mean) * (x1 - mean);
    #pragma unroll
    for (int o = 16; o; o >>= 1) vv += __shfl_xor_sync(0xffffffffu, vv, o);
    float inv = rsqrtf(vv * (1.f / 64.f) + 1e-5f);

    float h0n = (x0 - mean) * inv * lng[l * HIDN + lane]      + lnb[l * HIDN + lane];
    float h1n = (x1 - mean) * inv * lng[l * HIDN + lane + 32] + lnb[l * HIDN + lane + 32];
    if (!last) {
        g_h[n * HIDN + lane]      = h0n;
        g_h[n * HIDN + lane + 32] = h1n;
    }

    // projection (next-layer transform, or output projection)
    float a0 = last ? bn[lane]      : 0.f;
    float a1 = last ? bn[lane + 32] : 0.f;
    #pragma unroll
    for (int k = 0; k < HIDN; k++) {
        float hk = (k < 32) ? __shfl_sync(0xffffffffu, h0n, k)
                            : __shfl_sync(0xffffffffu, h1n, k - 32);
        float2 w = ws[k * 32 + lane];
        a0 += hk * w.x;
        a1 += hk * w.y;
    }
    if (last) {
        outp[n * HIDN + lane]      = a0;
        outp[n * HIDN + lane + 32] = a1;
        return;
    }
    hw_out[n * HIDN + lane]      = a0;
    hw_out[n * HIDN + lane + 32] = a1;

    float rs0 = a0 * sa[lane], rs1 = a1 * sa[lane + 32];
    float rd0 = a0 * sd[lane], rd1 = a1 * sd[lane + 32];
    #pragma unroll
    for (int o = 8; o >= 1; o >>= 1) {
        rs0 += __shfl_xor_sync(0xffffffffu, rs0, o);
        rs1 += __shfl_xor_sync(0xffffffffu, rs1, o);
        rd0 += __shfl_xor_sync(0xffffffffu, rd0, o);
        rd1 += __shfl_xor_sync(0xffffffffu, rd1, o);
    }
    if (lane == 0)  { as_out[n*NHD+0] = rs0; as_out[n*NHD+2] = rs1;
                      ad_out[n*NHD+0] = rd0; ad_out[n*NHD+2] = rd1; }
    if (lane == 16) { as_out[n*NHD+1] = rs0; as_out[n*NHD+3] = rs1;
                      ad_out[n*NHD+1] = rd0; ad_out[n*NHD+3] = rd1; }
}

// ---------------------------------------------------------------------------
extern "C" void kernel_launch(void* const* d_in, const int* in_sizes, int n_in,
                              void* d_out, int out_size)
{
    const float* x        = (const float*)d_in[0];
    const int*   ei       = (const int*)d_in[1];     // int64 in ref -> int32 on device
    const float* ea       = (const float*)d_in[2];
    const float* w_ne1    = (const float*)d_in[3];
    const float* b_ne1    = (const float*)d_in[4];
    const float* w_ne2    = (const float*)d_in[5];
    const float* b_ne2    = (const float*)d_in[6];
    const float* w_ee     = (const float*)d_in[7];
    const float* b_ee     = (const float*)d_in[8];
    const float* w_gat    = (const float*)d_in[9];
    const float* w_eg     = (const float*)d_in[10];
    const float* att_src  = (const float*)d_in[11];
    const float* att_dst  = (const float*)d_in[12];
    const float* att_edge = (const float*)d_in[13];
    const float* b_gat    = (const float*)d_in[14];
    const float* ln_g     = (const float*)d_in[15];
    const float* ln_b     = (const float*)d_in[16];
    const float* w_out    = (const float*)d_in[17];
    const float* b_out    = (const float*)d_in[18];
    float*       out      = (float*)d_out;

    int nb = (NN + NPB - 1) / NPB;
    int eb = (EE + 255) / 256;

    float* g_hw0p;  cudaGetSymbolAddress((void**)&g_hw0p, g_hw0);
    float* g_hw1p;  cudaGetSymbolAddress((void**)&g_hw1p, g_hw1);
    float* g_as0p;  cudaGetSymbolAddress((void**)&g_as0p, g_as0);
    float* g_ad0p;  cudaGetSymbolAddress((void**)&g_ad0p, g_ad0);
    float* g_as1p;  cudaGetSymbolAddress((void**)&g_as1p, g_as1);
    float* g_ad1p;  cudaGetSymbolAddress((void**)&g_ad1p, g_ad1);

    k_const<<<NLY, HIDN>>>(w_ee, b_ee, w_eg, att_edge);

    // CSR build (amortized over 3 layers)
    k_zero<<<(NN + 255) / 256, 256>>>();
    k_count<<<eb, 256>>>(ei);
    k_scan1<<<SCAN_G, SCAN_B>>>();
    k_scan2<<<1, 128>>>();
    k_scan3<<<SCAN_G, SCAN_B>>>();
    k_scatter<<<eb, 256>>>(ei, ea);

    k_encode_t<<<nb, TPB>>>(x, w_ne1, b_ne1, w_ne2, b_ne2,
                            w_gat, att_src, att_dst);

    // layer 0: read hw0 -> write hw1
    k_gat<<<nb, TPB>>>(g_hw0p, g_as0p, g_ad0p, 0, b_gat, ln_g, ln_b,
                       w_gat + 1 * HIDN * HIDN,
                       att_src + 1 * NHD * DHD, att_dst + 1 * NHD * DHD,
                       nullptr, g_hw1p, g_as1p, g_ad1p, nullptr, 0);
    // layer 1: read hw1 -> write hw0
    k_gat<<<nb, TPB>>>(g_hw1p, g_as1p, g_ad1p, 1, b_gat, ln_g, ln_b,
                       w_gat + 2 * HIDN * HIDN,
                       att_src + 2 * NHD * DHD, att_dst + 2 * NHD * DHD,
                       nullptr, g_hw0p, g_as0p, g_ad0p, nullptr, 0);
    // layer 2 (last): read hw0 -> out = h @ w_out + b_out
    k_gat<<<nb, TPB>>>(g_hw0p, g_as0p, g_ad0p, 2, b_gat, ln_g, ln_b,
                       w_out, nullptr, nullptr, b_out,
                       nullptr, nullptr, nullptr, out, 1);
}

// round 8
// speedup vs baseline: 1.0397x; 1.0397x over previous
#include <cuda_runtime.h>

#define NN  100000
#define EE  1200000
#define HIDN 64
#define NHD 4
#define DHD 16
#define NLY 3
#define SCAN_B 1024
#define SCAN_G ((NN + SCAN_B - 1) / SCAN_B)   // 98
#define NPB 16                                 // nodes (warps) per block
#define TPB (NPB * 32)                         // 512 threads
#define FULLM 0xffffffffu

// ---- scratch (static device globals) ----
__device__ float g_h[NN * HIDN];        // node features between layers
__device__ float g_hw0[NN * HIDN];      // transformed features (ping)
__device__ float g_hw1[NN * HIDN];      // transformed features (pong)
__device__ float g_as0[NN * NHD], g_ad0[NN * NHD];
__device__ float g_as1[NN * NHD], g_ad1[NN * NHD];
__device__ float g_c0[NLY * NHD], g_c1[NLY * NHD];
// CSR by destination: packed (src, ea-bits)
__device__ int   g_deg[NN];
__device__ int   g_rs[NN];
__device__ int   g_cur[NN];
__device__ int2  g_cse[EE];
__device__ int   g_psum[SCAN_G];

// ---------------------------------------------------------------------------
// Edge-attn constants (edge encoder is rank-1 since EIN=1):
// a_e[e,h] = ea[e]*c1[l,h] + c0[l,h]
// ---------------------------------------------------------------------------
__global__ void k_const(const float* __restrict__ w_ee, const float* __restrict__ b_ee,
                        const float* __restrict__ w_eg, const float* __restrict__ att_e)
{
    int l = blockIdx.x, j = threadIdx.x;
    __shared__ float sU[HIDN], sV[HIDN];
    const float* W = w_eg + l * HIDN * HIDN;
    float U = 0.f, V = 0.f;
    for (int k = 0; k < HIDN; k++) {
        float wk = W[k * HIDN + j];
        U += w_ee[k] * wk;
        V += b_ee[k] * wk;
    }
    sU[j] = U; sV[j] = V;
    __syncthreads();
    if (j < NHD) {
        float c1 = 0.f, c0 = 0.f;
        for (int d = 0; d < DHD; d++) {
            float a = att_e[l * HIDN + j * DHD + d];
            c1 += sU[j * DHD + d] * a;
            c0 += sV[j * DHD + d] * a;
        }
        g_c1[l * NHD + j] = c1;
        g_c0[l * NHD + j] = c0;
    }
}

// ---------------------------------------------------------------------------
// CSR build: zero -> count -> scan -> scatter (packed int2)
// ---------------------------------------------------------------------------
__global__ void k_zero()
{
    int i = blockIdx.x * blockDim.x + threadIdx.x;
    if (i < NN) g_deg[i] = 0;
}

__global__ void k_count(const int* __restrict__ ei)
{
    int e = blockIdx.x * blockDim.x + threadIdx.x;
    if (e < EE) atomicAdd(&g_deg[ei[EE + e]], 1);
}

__global__ void k_scan1()
{
    __shared__ int s[SCAN_B];
    int t = threadIdx.x, gid = blockIdx.x * SCAN_B + t;
    int v = (gid < NN) ? g_deg[gid] : 0;
    s[t] = v;
    __syncthreads();
    #pragma unroll
    for (int off = 1; off < SCAN_B; off <<= 1) {
        int u = (t >= off) ? s[t - off] : 0;
        __syncthreads();
        s[t] += u;
        __syncthreads();
    }
    if (gid < NN) g_rs[gid] = s[t] - v;            // exclusive within block
    if (t == SCAN_B - 1) g_psum[blockIdx.x] = s[t];
}

__global__ void k_scan2()
{
    __shared__ int s[SCAN_G];
    int t = threadIdx.x;
    int v = (t < SCAN_G) ? g_psum[t] : 0;
    if (t < SCAN_G) s[t] = v;
    __syncthreads();
    for (int off = 1; off < SCAN_G; off <<= 1) {
        int u = (t >= off && t < SCAN_G) ? s[t - off] : 0;
        __syncthreads();
        if (t < SCAN_G) s[t] += u;
        __syncthreads();
    }
    if (t < SCAN_G) g_psum[t] = s[t] - v;          // exclusive
}

__global__ void k_scan3()
{
    int gid = blockIdx.x * SCAN_B + threadIdx.x;
    if (gid < NN) {
        g_rs[gid] += g_psum[blockIdx.x];
        g_cur[gid] = 0;
    }
}

__global__ void k_scatter(const int* __restrict__ ei, const float* __restrict__ ea)
{
    int e = blockIdx.x * blockDim.x + threadIdx.x;
    if (e >= EE) return;
    int dst = ei[EE + e];
    int pos = g_rs[dst] + atomicAdd(&g_cur[dst], 1);
    g_cse[pos] = make_int2(ei[e], __float_as_int(ea[e]));
}

// ---------------------------------------------------------------------------
// Fused node encoder + layer-0 transform. One warp per node.
// ---------------------------------------------------------------------------
__global__ void __launch_bounds__(TPB)
k_encode_t(const float* __restrict__ x,
           const float* __restrict__ w1, const float* __restrict__ b1,
           const float* __restrict__ w2, const float* __restrict__ b2,
           const float* __restrict__ wg0,
           const float* __restrict__ atts, const float* __restrict__ attd)
{
    __shared__ float2 w2s[HIDN * 32];
    __shared__ float2 wgs[HIDN * 32];
    __shared__ float sa[HIDN], sd[HIDN];
    int tid = threadIdx.x;
    for (int i = tid; i < HIDN * 32; i += TPB) {
        int k = i >> 5, c = i & 31;
        w2s[i] = make_float2(w2[k * HIDN + c],  w2[k * HIDN + c + 32]);
        wgs[i] = make_float2(wg0[k * HIDN + c], wg0[k * HIDN + c + 32]);
    }
    if (tid < HIDN) { sa[tid] = atts[tid]; sd[tid] = attd[tid]; }
    __syncthreads();

    int warp = tid >> 5, lane = tid & 31;
    int n = blockIdx.x * NPB + warp;
    if (n >= NN) return;

    float xv[6];
    #pragma unroll
    for (int k = 0; k < 6; k++) xv[k] = x[n * 6 + k];
    float h0 = b1[lane], h1 = b1[lane + 32];
    #pragma unroll
    for (int k = 0; k < 6; k++) {
        h0 += xv[k] * w1[k * HIDN + lane];
        h1 += xv[k] * w1[k * HIDN + lane + 32];
    }
    h0 = fmaxf(h0, 0.f); h1 = fmaxf(h1, 0.f);

    float a0 = b2[lane], a1 = b2[lane + 32];
    #pragma unroll
    for (int k = 0; k < HIDN; k++) {
        float hk = (k < 32) ? __shfl_sync(FULLM, h0, k)
                            : __shfl_sync(FULLM, h1, k - 32);
        float2 w = w2s[k * 32 + lane];
        a0 += hk * w.x;
        a1 += hk * w.y;
    }
    g_h[n * HIDN + lane]      = a0;
    g_h[n * HIDN + lane + 32] = a1;

    float t0 = 0.f, t1 = 0.f;
    #pragma unroll
    for (int k = 0; k < HIDN; k++) {
        float hk = (k < 32) ? __shfl_sync(FULLM, a0, k)
                            : __shfl_sync(FULLM, a1, k - 32);
        float2 w = wgs[k * 32 + lane];
        t0 += hk * w.x;
        t1 += hk * w.y;
    }
    g_hw0[n * HIDN + lane]      = t0;
    g_hw0[n * HIDN + lane + 32] = t1;

    float rs0 = t0 * sa[lane], rs1 = t1 * sa[lane + 32];
    float rd0 = t0 * sd[lane], rd1 = t1 * sd[lane + 32];
    #pragma unroll
    for (int o = 8; o >= 1; o >>= 1) {
        rs0 += __shfl_xor_sync(FULLM, rs0, o);
        rs1 += __shfl_xor_sync(FULLM, rs1, o);
        rd0 += __shfl_xor_sync(FULLM, rd0, o);
        rd1 += __shfl_xor_sync(FULLM, rd1, o);
    }
    if (lane == 0)  { g_as0[n*NHD+0] = rs0; g_as0[n*NHD+2] = rs1;
                      g_ad0[n*NHD+0] = rd0; g_ad0[n*NHD+2] = rd1; }
    if (lane == 16) { g_as0[n*NHD+1] = rs0; g_as0[n*NHD+3] = rs1;
                      g_ad0[n*NHD+1] = rd0; g_ad0[n*NHD+3] = rd1; }
}

// ---------------------------------------------------------------------------
// Fused GAT layer: one warp per destination node.
// Edge loop: lane = slot*8 + t; 4 edge slots in parallel, lane t owns
// channels t*8..t*8+7 of its slot's edge. NO shuffles in the loop body:
// every lane loads cse/as/hw itself. Post-loop XOR reduction over slots,
// then a per-warp smem transpose back to the 2-channels-per-lane layout
// for the ELU/LN/projection epilogue.
// ---------------------------------------------------------------------------
__global__ void __launch_bounds__(TPB)
k_gat(const float* __restrict__ hw_in,
      const float* __restrict__ as_in, const float* __restrict__ ad_in,
      int l,
      const float* __restrict__ b_gat,
      const float* __restrict__ lng, const float* __restrict__ lnb,
      const float* __restrict__ Wn,
      const float* __restrict__ atts, const float* __restrict__ attd,
      const float* __restrict__ bn,
      float* __restrict__ hw_out,
      float* __restrict__ as_out, float* __restrict__ ad_out,
      float* __restrict__ outp, int last)
{
    __shared__ float2 ws[HIDN * 32];
    __shared__ float sa[HIDN], sd[HIDN];
    __shared__ float tb[NPB][HIDN];
    int tid = threadIdx.x;
    for (int i = tid; i < HIDN * 32; i += TPB) {
        int k = i >> 5, c = i & 31;
        ws[i] = make_float2(Wn[k * HIDN + c], Wn[k * HIDN + c + 32]);
    }
    if (!last && tid < HIDN) { sa[tid] = atts[tid]; sd[tid] = attd[tid]; }
    __syncthreads();

    int warp = tid >> 5, lane = tid & 31;
    int n = blockIdx.x * NPB + warp;
    if (n >= NN) return;

    int t    = lane & 7;                     // channel-slice owner (0..7)
    int slot = lane >> 3;                    // edge slot (0..3)
    int head = t >> 1;                       // head of channels t*8..t*8+7
    float c1h = g_c1[l * NHD + head], c0h = g_c0[l * NHD + head];
    float adh = ad_in[n * NHD + head];
    int base = g_rs[n], dg = g_deg[n];

    const float4* as4 = (const float4*)as_in;

    float acc[8];
    #pragma unroll
    for (int i = 0; i < 8; i++) acc[i] = 0.f;
    float den = 0.f;

    for (int off = 0; off < dg; off += 8) {
        // ---- half A: edge index off + slot ----
        {
            int idx = off + slot;
            bool v = idx < dg;
            int2 se = g_cse[base + (v ? idx : 0)];
            int src = v ? se.x : 0;
            float4 av = as4[src];
            float asv = (head == 0) ? av.x : (head == 1) ? av.y
                      : (head == 2) ? av.z : av.w;
            float s = asv + adh + __int_as_float(se.y) * c1h + c0h;
            s = (s > 0.f) ? s : 0.2f * s;
            float ex = v ? __expf(s) : 0.f;
            den += ex;
            const float4* hp = (const float4*)(hw_in + src * HIDN + t * 8);
            float4 p = hp[0], q = hp[1];
            acc[0] += ex * p.x; acc[1] += ex * p.y;
            acc[2] += ex * p.z; acc[3] += ex * p.w;
            acc[4] += ex * q.x; acc[5] += ex * q.y;
            acc[6] += ex * q.z; acc[7] += ex * q.w;
        }
        // ---- half B: edge index off + 4 + slot ----
        {
            int idx = off + 4 + slot;
            bool v = idx < dg;
            int2 se = g_cse[base + (v ? idx : 0)];
            int src = v ? se.x : 0;
            float4 av = as4[src];
            float asv = (head == 0) ? av.x : (head == 1) ? av.y
                      : (head == 2) ? av.z : av.w;
            float s = asv + adh + __int_as_float(se.y) * c1h + c0h;
            s = (s > 0.f) ? s : 0.2f * s;
            float ex = v ? __expf(s) : 0.f;
            den += ex;
            const float4* hp = (const float4*)(hw_in + src * HIDN + t * 8);
            float4 p = hp[0], q = hp[1];
            acc[0] += ex * p.x; acc[1] += ex * p.y;
            acc[2] += ex * p.z; acc[3] += ex * p.w;
            acc[4] += ex * q.x; acc[5] += ex * q.y;
            acc[6] += ex * q.z; acc[7] += ex * q.w;
        }
    }

    // reduce over the 4 edge slots (lanes differing in bits 3,4)
    #pragma unroll
    for (int i = 0; i < 8; i++) {
        acc[i] += __shfl_xor_sync(FULLM, acc[i], 8);
        acc[i] += __shfl_xor_sync(FULLM, acc[i], 16);
    }
    den += __shfl_xor_sync(FULLM, den, 8);
    den += __shfl_xor_sync(FULLM, den, 16);

    // transpose to 2-channels-per-lane layout via per-warp smem buffer
    if (lane < 8) {
        float4* tp = (float4*)&tb[warp][lane * 8];
        tp[0] = make_float4(acc[0], acc[1], acc[2], acc[3]);
        tp[1] = make_float4(acc[4], acc[5], acc[6], acc[7]);
    }
    __syncwarp();
    float num0 = tb[warp][lane];
    float num1 = tb[warp][lane + 32];
    // den for head of channel `lane` is held at lane 2*head (t=2h, slot 0)
    float d0 = __shfl_sync(FULLM, den, 2 * (lane >> 4));
    float d1 = __shfl_sync(FULLM, den, 4 + 2 * (lane >> 4));

    float v0 = num0 / (d0 + 1e-16f) + b_gat[l * HIDN + lane];
    float v1 = num1 / (d1 + 1e-16f) + b_gat[l * HIDN + lane + 32];
    v0 = (v0 > 0.f) ? v0 : expm1f(v0);
    v1 = (v1 > 0.f) ? v1 : expm1f(v1);

    float x0 = g_h[n * HIDN + lane]      + v0;
    float x1 = g_h[n * HIDN + lane + 32] + v1;

    float s = x0 + x1;
    #pragma unroll
    for (int o = 16; o; o >>= 1) s += __shfl_xor_sync(FULLM, s, o);
    float mean = s * (1.f / 64.f);
    float vv = (x0 - mean) * (x0 - mean) + (x1 - mean) * (x1 - mean);
    #pragma unroll
    for (int o = 16; o; o >>= 1) vv += __shfl_xor_sync(FULLM, vv, o);
    float inv = rsqrtf(vv * (1.f / 64.f) + 1e-5f);

    float h0n = (x0 - mean) * inv * lng[l * HIDN + lane]      + lnb[l * HIDN + lane];
    float h1n = (x1 - mean) * inv * lng[l * HIDN + lane + 32] + lnb[l * HIDN + lane + 32];
    if (!last) {
        g_h[n * HIDN + lane]      = h0n;
        g_h[n * HIDN + lane + 32] = h1n;
    }

    // projection (next-layer transform, or output projection)
    float a0 = last ? bn[lane]      : 0.f;
    float a1 = last ? bn[lane + 32] : 0.f;
    #pragma unroll
    for (int k = 0; k < HIDN; k++) {
        float hk = (k < 32) ? __shfl_sync(FULLM, h0n, k)
                            : __shfl_sync(FULLM, h1n, k - 32);
        float2 w = ws[k * 32 + lane];
        a0 += hk * w.x;
        a1 += hk * w.y;
    }
    if (last) {
        outp[n * HIDN + lane]      = a0;
        outp[n * HIDN + lane + 32] = a1;
        return;
    }
    hw_out[n * HIDN + lane]      = a0;
    hw_out[n * HIDN + lane + 32] = a1;

    float rs0 = a0 * sa[lane], rs1 = a1 * sa[lane + 32];
    float rd0 = a0 * sd[lane], rd1 = a1 * sd[lane + 32];
    #pragma unroll
    for (int o = 8; o >= 1; o >>= 1) {
        rs0 += __shfl_xor_sync(FULLM, rs0, o);
        rs1 += __shfl_xor_sync(FULLM, rs1, o);
        rd0 += __shfl_xor_sync(FULLM, rd0, o);
        rd1 += __shfl_xor_sync(FULLM, rd1, o);
    }
    if (lane == 0)  { as_out[n*NHD+0] = rs0; as_out[n*NHD+2] = rs1;
                      ad_out[n*NHD+0] = rd0; ad_out[n*NHD+2] = rd1; }
    if (lane == 16) { as_out[n*NHD+1] = rs0; as_out[n*NHD+3] = rs1;
                      ad_out[n*NHD+1] = rd0; ad_out[n*NHD+3] = rd1; }
}

// ---------------------------------------------------------------------------
extern "C" void kernel_launch(void* const* d_in, const int* in_sizes, int n_in,
                              void* d_out, int out_size)
{
    const float* x        = (const float*)d_in[0];
    const int*   ei       = (const int*)d_in[1];     // int64 in ref -> int32 on device
    const float* ea       = (const float*)d_in[2];
    const float* w_ne1    = (const float*)d_in[3];
    const float* b_ne1    = (const float*)d_in[4];
    const float* w_ne2    = (const float*)d_in[5];
    const float* b_ne2    = (const float*)d_in[6];
    const float* w_ee     = (const float*)d_in[7];
    const float* b_ee     = (const float*)d_in[8];
    const float* w_gat    = (const float*)d_in[9];
    const float* w_eg     = (const float*)d_in[10];
    const float* att_src  = (const float*)d_in[11];
    const float* att_dst  = (const float*)d_in[12];
    const float* att_edge = (const float*)d_in[13];
    const float* b_gat    = (const float*)d_in[14];
    const float* ln_g     = (const float*)d_in[15];
    const float* ln_b     = (const float*)d_in[16];
    const float* w_out    = (const float*)d_in[17];
    const float* b_out    = (const float*)d_in[18];
    float*       out      = (float*)d_out;

    int nb = (NN + NPB - 1) / NPB;
    int eb = (EE + 255) / 256;

    float* g_hw0p;  cudaGetSymbolAddress((void**)&g_hw0p, g_hw0);
    float* g_hw1p;  cudaGetSymbolAddress((void**)&g_hw1p, g_hw1);
    float* g_as0p;  cudaGetSymbolAddress((void**)&g_as0p, g_as0);
    float* g_ad0p;  cudaGetSymbolAddress((void**)&g_ad0p, g_ad0);
    float* g_as1p;  cudaGetSymbolAddress((void**)&g_as1p, g_as1);
    float* g_ad1p;  cudaGetSymbolAddress((void**)&g_ad1p, g_ad1);

    k_const<<<NLY, HIDN>>>(w_ee, b_ee, w_eg, att_edge);

    // CSR build (amortized over 3 layers)
    k_zero<<<(NN + 255) / 256, 256>>>();
    k_count<<<eb, 256>>>(ei);
    k_scan1<<<SCAN_G, SCAN_B>>>();
    k_scan2<<<1, 128>>>();
    k_scan3<<<SCAN_G, SCAN_B>>>();
    k_scatter<<<eb, 256>>>(ei, ea);

    k_encode_t<<<nb, TPB>>>(x, w_ne1, b_ne1, w_ne2, b_ne2,
                            w_gat, att_src, att_dst);

    // layer 0: read hw0 -> write hw1
    k_gat<<<nb, TPB>>>(g_hw0p, g_as0p, g_ad0p, 0, b_gat, ln_g, ln_b,
                       w_gat + 1 * HIDN * HIDN,
                       att_src + 1 * NHD * DHD, att_dst + 1 * NHD * DHD,
                       nullptr, g_hw1p, g_as1p, g_ad1p, nullptr, 0);
    // layer 1: read hw1 -> write hw0
    k_gat<<<nb, TPB>>>(g_hw1p, g_as1p, g_ad1p, 1, b_gat, ln_g, ln_b,
                       w_gat + 2 * HIDN * HIDN,
                       att_src + 2 * NHD * DHD, att_dst + 2 * NHD * DHD,
                       nullptr, g_hw0p, g_as0p, g_ad0p, nullptr, 0);
    // layer 2 (last): read hw0 -> out = h @ w_out + b_out
    k_gat<<<nb, TPB>>>(g_hw0p, g_as0p, g_ad0p, 2, b_gat, ln_g, ln_b,
                       w_out, nullptr, nullptr, b_out,
                       nullptr, nullptr, nullptr, out, 1);
}

// round 9
// speedup vs baseline: 1.3150x; 1.2648x over previous
#include <cuda_runtime.h>

#define NN  100000
#define EE  1200000
#define HIDN 64
#define NHD 4
#define DHD 16
#define NLY 3
#define SCAN_B 1024
#define SCAN_G ((NN + SCAN_B - 1) / SCAN_B)   // 98
#define NPB 16                                 // nodes (warps) per block (edge kernel)
#define TPB (NPB * 32)                         // 512 threads
#define FULLM 0xffffffffu
#define MT 64                                  // GEMM tile: 64 nodes x 64 ch
#define GB ((NN + MT - 1) / MT)                // 1563 tiles

// ---- scratch (static device globals) ----
__device__ float g_h[NN * HIDN];        // node features between layers
__device__ float g_hw0[NN * HIDN];      // transformed features (ping)
__device__ float g_hw1[NN * HIDN];      // transformed features (pong)
__device__ float g_as0[NN * NHD], g_ad0[NN * NHD];
__device__ float g_as1[NN * NHD], g_ad1[NN * NHD];
__device__ float g_c0[NLY * NHD], g_c1[NLY * NHD];
// CSR by destination: packed (src, ea-bits)
__device__ int   g_deg[NN];
__device__ int   g_rs[NN];
__device__ int   g_cur[NN];
__device__ int2  g_cse[EE];
__device__ int   g_psum[SCAN_G];

// ---------------------------------------------------------------------------
// Edge-attn constants (edge encoder is rank-1 since EIN=1):
// a_e[e,h] = ea[e]*c1[l,h] + c0[l,h]
// ---------------------------------------------------------------------------
__global__ void k_const(const float* __restrict__ w_ee, const float* __restrict__ b_ee,
                        const float* __restrict__ w_eg, const float* __restrict__ att_e)
{
    int l = blockIdx.x, j = threadIdx.x;
    __shared__ float sU[HIDN], sV[HIDN];
    const float* W = w_eg + l * HIDN * HIDN;
    float U = 0.f, V = 0.f;
    for (int k = 0; k < HIDN; k++) {
        float wk = W[k * HIDN + j];
        U += w_ee[k] * wk;
        V += b_ee[k] * wk;
    }
    sU[j] = U; sV[j] = V;
    __syncthreads();
    if (j < NHD) {
        float c1 = 0.f, c0 = 0.f;
        for (int d = 0; d < DHD; d++) {
            float a = att_e[l * HIDN + j * DHD + d];
            c1 += sU[j * DHD + d] * a;
            c0 += sV[j * DHD + d] * a;
        }
        g_c1[l * NHD + j] = c1;
        g_c0[l * NHD + j] = c0;
    }
}

// ---------------------------------------------------------------------------
// CSR build: zero -> count -> scan -> scatter (packed int2)
// ---------------------------------------------------------------------------
__global__ void k_zero()
{
    int i = blockIdx.x * blockDim.x + threadIdx.x;
    if (i < NN) g_deg[i] = 0;
}

__global__ void k_count(const int* __restrict__ ei)
{
    int e = blockIdx.x * blockDim.x + threadIdx.x;
    if (e < EE) atomicAdd(&g_deg[ei[EE + e]], 1);
}

__global__ void k_scan1()
{
    __shared__ int s[SCAN_B];
    int t = threadIdx.x, gid = blockIdx.x * SCAN_B + t;
    int v = (gid < NN) ? g_deg[gid] : 0;
    s[t] = v;
    __syncthreads();
    #pragma unroll
    for (int off = 1; off < SCAN_B; off <<= 1) {
        int u = (t >= off) ? s[t - off] : 0;
        __syncthreads();
        s[t] += u;
        __syncthreads();
    }
    if (gid < NN) g_rs[gid] = s[t] - v;            // exclusive within block
    if (t == SCAN_B - 1) g_psum[blockIdx.x] = s[t];
}

__global__ void k_scan2()
{
    __shared__ int s[SCAN_G];
    int t = threadIdx.x;
    int v = (t < SCAN_G) ? g_psum[t] : 0;
    if (t < SCAN_G) s[t] = v;
    __syncthreads();
    for (int off = 1; off < SCAN_G; off <<= 1) {
        int u = (t >= off && t < SCAN_G) ? s[t - off] : 0;
        __syncthreads();
        if (t < SCAN_G) s[t] += u;
        __syncthreads();
    }
    if (t < SCAN_G) g_psum[t] = s[t] - v;          // exclusive
}

__global__ void k_scan3()
{
    int gid = blockIdx.x * SCAN_B + threadIdx.x;
    if (gid < NN) {
        g_rs[gid] += g_psum[blockIdx.x];
        g_cur[gid] = 0;
    }
}

__global__ void k_scatter(const int* __restrict__ ei, const float* __restrict__ ea)
{
    int e = blockIdx.x * blockDim.x + threadIdx.x;
    if (e >= EE) return;
    int dst = ei[EE + e];
    int pos = g_rs[dst] + atomicAdd(&g_cur[dst], 1);
    g_cse[pos] = make_int2(ei[e], __float_as_int(ea[e]));
}

// ---------------------------------------------------------------------------
// Fused node encoder + layer-0 transform. One warp per node.
// ---------------------------------------------------------------------------
__global__ void __launch_bounds__(TPB)
k_encode_t(const float* __restrict__ x,
           const float* __restrict__ w1, const float* __restrict__ b1,
           const float* __restrict__ w2, const float* __restrict__ b2,
           const float* __restrict__ wg0,
           const float* __restrict__ atts, const float* __restrict__ attd)
{
    __shared__ float2 w2s[HIDN * 32];
    __shared__ float2 wgs[HIDN * 32];
    __shared__ float sa[HIDN], sd[HIDN];
    int tid = threadIdx.x;
    for (int i = tid; i < HIDN * 32; i += TPB) {
        int k = i >> 5, c = i & 31;
        w2s[i] = make_float2(w2[k * HIDN + c],  w2[k * HIDN + c + 32]);
        wgs[i] = make_float2(wg0[k * HIDN + c], wg0[k * HIDN + c + 32]);
    }
    if (tid < HIDN) { sa[tid] = atts[tid]; sd[tid] = attd[tid]; }
    __syncthreads();

    int warp = tid >> 5, lane = tid & 31;
    int n = blockIdx.x * NPB + warp;
    if (n >= NN) return;

    float xv[6];
    #pragma unroll
    for (int k = 0; k < 6; k++) xv[k] = x[n * 6 + k];
    float h0 = b1[lane], h1 = b1[lane + 32];
    #pragma unroll
    for (int k = 0; k < 6; k++) {
        h0 += xv[k] * w1[k * HIDN + lane];
        h1 += xv[k] * w1[k * HIDN + lane + 32];
    }
    h0 = fmaxf(h0, 0.f); h1 = fmaxf(h1, 0.f);

    float a0 = b2[lane], a1 = b2[lane + 32];
    #pragma unroll
    for (int k = 0; k < HIDN; k++) {
        float hk = (k < 32) ? __shfl_sync(FULLM, h0, k)
                            : __shfl_sync(FULLM, h1, k - 32);
        float2 w = w2s[k * 32 + lane];
        a0 += hk * w.x;
        a1 += hk * w.y;
    }
    g_h[n * HIDN + lane]      = a0;
    g_h[n * HIDN + lane + 32] = a1;

    float t0 = 0.f, t1 = 0.f;
    #pragma unroll
    for (int k = 0; k < HIDN; k++) {
        float hk = (k < 32) ? __shfl_sync(FULLM, a0, k)
                            : __shfl_sync(FULLM, a1, k - 32);
        float2 w = wgs[k * 32 + lane];
        t0 += hk * w.x;
        t1 += hk * w.y;
    }
    g_hw0[n * HIDN + lane]      = t0;
    g_hw0[n * HIDN + lane + 32] = t1;

    float rs0 = t0 * sa[lane], rs1 = t1 * sa[lane + 32];
    float rd0 = t0 * sd[lane], rd1 = t1 * sd[lane + 32];
    #pragma unroll
    for (int o = 8; o >= 1; o >>= 1) {
        rs0 += __shfl_xor_sync(FULLM, rs0, o);
        rs1 += __shfl_xor_sync(FULLM, rs1, o);
        rd0 += __shfl_xor_sync(FULLM, rd0, o);
        rd1 += __shfl_xor_sync(FULLM, rd1, o);
    }
    if (lane == 0)  { g_as0[n*NHD+0] = rs0; g_as0[n*NHD+2] = rs1;
                      g_ad0[n*NHD+0] = rd0; g_ad0[n*NHD+2] = rd1; }
    if (lane == 16) { g_as0[n*NHD+1] = rs0; g_as0[n*NHD+3] = rs1;
                      g_ad0[n*NHD+1] = rd0; g_ad0[n*NHD+3] = rd1; }
}

// ---------------------------------------------------------------------------
// Edge aggregation + node update (NO projection): one warp per dst node.
// R8 edge loop (lane = slot*8 + t, no shuffles in body), then
// normalize + bias + ELU + residual + LayerNorm -> g_h in place.
// ---------------------------------------------------------------------------
__global__ void __launch_bounds__(TPB)
k_edge_agg(const float* __restrict__ hw_in,
           const float* __restrict__ as_in, const float* __restrict__ ad_in,
           int l,
           const float* __restrict__ b_gat,
           const float* __restrict__ lng, const float* __restrict__ lnb)
{
    __shared__ float tb[NPB][HIDN];
    int tid = threadIdx.x;
    int warp = tid >> 5, lane = tid & 31;
    int n = blockIdx.x * NPB + warp;
    if (n >= NN) return;

    int t    = lane & 7;                     // channel-slice owner (0..7)
    int slot = lane >> 3;                    // edge slot (0..3)
    int head = t >> 1;                       // head of channels t*8..t*8+7
    float c1h = g_c1[l * NHD + head], c0h = g_c0[l * NHD + head];
    float adh = ad_in[n * NHD + head];
    int base = g_rs[n], dg = g_deg[n];

    const float4* as4 = (const float4*)as_in;

    float acc[8];
    #pragma unroll
    for (int i = 0; i < 8; i++) acc[i] = 0.f;
    float den = 0.f;

    for (int off = 0; off < dg; off += 8) {
        {
            int idx = off + slot;
            bool v = idx < dg;
            int2 se = g_cse[base + (v ? idx : 0)];
            int src = v ? se.x : 0;
            float4 av = as4[src];
            float asv = (head == 0) ? av.x : (head == 1) ? av.y
                      : (head == 2) ? av.z : av.w;
            float s = asv + adh + __int_as_float(se.y) * c1h + c0h;
            s = (s > 0.f) ? s : 0.2f * s;
            float ex = v ? __expf(s) : 0.f;
            den += ex;
            const float4* hp = (const float4*)(hw_in + src * HIDN + t * 8);
            float4 p = hp[0], q = hp[1];
            acc[0] += ex * p.x; acc[1] += ex * p.y;
            acc[2] += ex * p.z; acc[3] += ex * p.w;
            acc[4] += ex * q.x; acc[5] += ex * q.y;
            acc[6] += ex * q.z; acc[7] += ex * q.w;
        }
        {
            int idx = off + 4 + slot;
            bool v = idx < dg;
            int2 se = g_cse[base + (v ? idx : 0)];
            int src = v ? se.x : 0;
            float4 av = as4[src];
            float asv = (head == 0) ? av.x : (head == 1) ? av.y
                      : (head == 2) ? av.z : av.w;
            float s = asv + adh + __int_as_float(se.y) * c1h + c0h;
            s = (s > 0.f) ? s : 0.2f * s;
            float ex = v ? __expf(s) : 0.f;
            den += ex;
            const float4* hp = (const float4*)(hw_in + src * HIDN + t * 8);
            float4 p = hp[0], q = hp[1];
            acc[0] += ex * p.x; acc[1] += ex * p.y;
            acc[2] += ex * p.z; acc[3] += ex * p.w;
            acc[4] += ex * q.x; acc[5] += ex * q.y;
            acc[6] += ex * q.z; acc[7] += ex * q.w;
        }
    }

    // reduce over the 4 edge slots (lanes differing in bits 3,4)
    #pragma unroll
    for (int i = 0; i < 8; i++) {
        acc[i] += __shfl_xor_sync(FULLM, acc[i], 8);
        acc[i] += __shfl_xor_sync(FULLM, acc[i], 16);
    }
    den += __shfl_xor_sync(FULLM, den, 8);
    den += __shfl_xor_sync(FULLM, den, 16);

    // transpose to 2-channels-per-lane layout via per-warp smem buffer
    if (lane < 8) {
        float4* tp = (float4*)&tb[warp][lane * 8];
        tp[0] = make_float4(acc[0], acc[1], acc[2], acc[3]);
        tp[1] = make_float4(acc[4], acc[5], acc[6], acc[7]);
    }
    __syncwarp();
    float num0 = tb[warp][lane];
    float num1 = tb[warp][lane + 32];
    float d0 = __shfl_sync(FULLM, den, 2 * (lane >> 4));
    float d1 = __shfl_sync(FULLM, den, 4 + 2 * (lane >> 4));

    float v0 = num0 / (d0 + 1e-16f) + b_gat[l * HIDN + lane];
    float v1 = num1 / (d1 + 1e-16f) + b_gat[l * HIDN + lane + 32];
    v0 = (v0 > 0.f) ? v0 : expm1f(v0);
    v1 = (v1 > 0.f) ? v1 : expm1f(v1);

    float x0 = g_h[n * HIDN + lane]      + v0;
    float x1 = g_h[n * HIDN + lane + 32] + v1;

    float s = x0 + x1;
    #pragma unroll
    for (int o = 16; o; o >>= 1) s += __shfl_xor_sync(FULLM, s, o);
    float mean = s * (1.f / 64.f);
    float vv = (x0 - mean) * (x0 - mean) + (x1 - mean) * (x1 - mean);
    #pragma unroll
    for (int o = 16; o; o >>= 1) vv += __shfl_xor_sync(FULLM, vv, o);
    float inv = rsqrtf(vv * (1.f / 64.f) + 1e-5f);

    g_h[n * HIDN + lane]      = (x0 - mean) * inv * lng[l * HIDN + lane]      + lnb[l * HIDN + lane];
    g_h[n * HIDN + lane + 32] = (x1 - mean) * inv * lng[l * HIDN + lane + 32] + lnb[l * HIDN + lane + 32];
}

// ---------------------------------------------------------------------------
// Tiled projection GEMM: out[64-node tile][64] = h @ W (+bias).
// 256 threads, per-thread 4x4. h staged transposed hs[k][m]; W staged ws[k][c].
// mode 0: write hw + attention dots (as/ad). mode 1: write out with bias.
// ---------------------------------------------------------------------------
__global__ void __launch_bounds__(256)
k_project(const float* __restrict__ h, const float* __restrict__ W,
          const float* __restrict__ attS, const float* __restrict__ attD,
          const float* __restrict__ bias,
          float* __restrict__ o, float* __restrict__ as_o, float* __restrict__ ad_o,
          int mode)
{
    __shared__ float hs[HIDN][MT + 4];   // [k][m]
    __shared__ float ws[HIDN][HIDN + 4]; // [k][c]
    __shared__ float sa[HIDN], sd[HIDN];
    int tid = threadIdx.x;
    int m0 = blockIdx.x * MT;

    // stage h transposed: i -> m = i>>4, kq = i&15
    for (int i = tid; i < MT * 16; i += 256) {
        int m = i >> 4, kq = i & 15;
        float4 v = (m0 + m < NN) ? *(const float4*)(h + (size_t)(m0 + m) * HIDN + kq * 4)
                                 : make_float4(0.f, 0.f, 0.f, 0.f);
        hs[kq * 4 + 0][m] = v.x;
        hs[kq * 4 + 1][m] = v.y;
        hs[kq * 4 + 2][m] = v.z;
        hs[kq * 4 + 3][m] = v.w;
    }
    // stage W directly (k-major rows)
    for (int i = tid; i < HIDN * 16; i += 256) {
        int k = i >> 4, cq = i & 15;
        *(float4*)&ws[k][cq * 4] = *(const float4*)(W + k * HIDN + cq * 4);
    }
    if (mode == 0 && tid < HIDN) { sa[tid] = attS[tid]; sd[tid] = attD[tid]; }
    __syncthreads();

    int tx = tid & 15, ty = tid >> 4;        // tx: 4-ch group, ty: 4-node group
    float acc[4][4];
    #pragma unroll
    for (int i = 0; i < 4; i++)
        #pragma unroll
        for (int j = 0; j < 4; j++) acc[i][j] = 0.f;

    #pragma unroll
    for (int k = 0; k < HIDN; k++) {
        float4 hv = *(float4*)&hs[k][ty * 4];
        float4 wv = *(float4*)&ws[k][tx * 4];
        acc[0][0] += hv.x * wv.x; acc[0][1] += hv.x * wv.y;
        acc[0][2] += hv.x * wv.z; acc[0][3] += hv.x * wv.w;
        acc[1][0] += hv.y * wv.x; acc[1][1] += hv.y * wv.y;
        acc[1][2] += hv.y * wv.z; acc[1][3] += hv.y * wv.w;
        acc[2][0] += hv.z * wv.x; acc[2][1] += hv.z * wv.y;
        acc[2][2] += hv.z * wv.z; acc[2][3] += hv.z * wv.w;
        acc[3][0] += hv.w * wv.x; acc[3][1] += hv.w * wv.y;
        acc[3][2] += hv.w * wv.z; acc[3][3] += hv.w * wv.w;
    }

    if (mode == 1) {
        float4 bv = *(const float4*)(bias + tx * 4);
        #pragma unroll
        for (int mi = 0; mi < 4; mi++) {
            int n = m0 + ty * 4 + mi;
            if (n < NN)
                *(float4*)(o + (size_t)n * HIDN + tx * 4) =
                    make_float4(acc[mi][0] + bv.x, acc[mi][1] + bv.y,
                                acc[mi][2] + bv.z, acc[mi][3] + bv.w);
        }
        return;
    }

    // mode 0: store hw + attention dots
    #pragma unroll
    for (int mi = 0; mi < 4; mi++) {
        int n = m0 + ty * 4 + mi;
        if (n < NN)
            *(float4*)(o + (size_t)n * HIDN + tx * 4) =
                make_float4(acc[mi][0], acc[mi][1], acc[mi][2], acc[mi][3]);
    }
    // dots: channels tx*4..tx*4+3 all lie in head tx>>2
    float4 sav = *(float4*)&sa[tx * 4];
    float4 sdv = *(float4*)&sd[tx * 4];
    #pragma unroll
    for (int mi = 0; mi < 4; mi++) {
        float ps = acc[mi][0] * sav.x + acc[mi][1] * sav.y
                 + acc[mi][2] * sav.z + acc[mi][3] * sav.w;
        float pd = acc[mi][0] * sdv.x + acc[mi][1] * sdv.y
                 + acc[mi][2] * sdv.z + acc[mi][3] * sdv.w;
        // reduce over the 4 tx's of this head (lane bits 0,1)
        ps += __shfl_xor_sync(FULLM, ps, 1);
        ps += __shfl_xor_sync(FULLM, ps, 2);
        pd += __shfl_xor_sync(FULLM, pd, 1);
        pd += __shfl_xor_sync(FULLM, pd, 2);
        int n = m0 + ty * 4 + mi;
        if ((tx & 3) == 0 && n < NN) {
            as_o[n * NHD + (tx >> 2)] = ps;
            ad_o[n * NHD + (tx >> 2)] = pd;
        }
    }
}

// ---------------------------------------------------------------------------
extern "C" void kernel_launch(void* const* d_in, const int* in_sizes, int n_in,
                              void* d_out, int out_size)
{
    const float* x        = (const float*)d_in[0];
    const int*   ei       = (const int*)d_in[1];     // int64 in ref -> int32 on device
    const float* ea       = (const float*)d_in[2];
    const float* w_ne1    = (const float*)d_in[3];
    const float* b_ne1    = (const float*)d_in[4];
    const float* w_ne2    = (const float*)d_in[5];
    const float* b_ne2    = (const float*)d_in[6];
    const float* w_ee     = (const float*)d_in[7];
    const float* b_ee     = (const float*)d_in[8];
    const float* w_gat    = (const float*)d_in[9];
    const float* w_eg     = (const float*)d_in[10];
    const float* att_src  = (const float*)d_in[11];
    const float* att_dst  = (const float*)d_in[12];
    const float* att_edge = (const float*)d_in[13];
    const float* b_gat    = (const float*)d_in[14];
    const float* ln_g     = (const float*)d_in[15];
    const float* ln_b     = (const float*)d_in[16];
    const float* w_out    = (const float*)d_in[17];
    const float* b_out    = (const float*)d_in[18];
    float*       out      = (float*)d_out;

    int nb = (NN + NPB - 1) / NPB;
    int eb = (EE + 255) / 256;

    float* g_hp;    cudaGetSymbolAddress((void**)&g_hp,   g_h);
    float* g_hw0p;  cudaGetSymbolAddress((void**)&g_hw0p, g_hw0);
    float* g_hw1p;  cudaGetSymbolAddress((void**)&g_hw1p, g_hw1);
    float* g_as0p;  cudaGetSymbolAddress((void**)&g_as0p, g_as0);
    float* g_ad0p;  cudaGetSymbolAddress((void**)&g_ad0p, g_ad0);
    float* g_as1p;  cudaGetSymbolAddress((void**)&g_as1p, g_as1);
    float* g_ad1p;  cudaGetSymbolAddress((void**)&g_ad1p, g_ad1);

    k_const<<<NLY, HIDN>>>(w_ee, b_ee, w_eg, att_edge);

    // CSR build (amortized over 3 layers)
    k_zero<<<(NN + 255) / 256, 256>>>();
    k_count<<<eb, 256>>>(ei);
    k_scan1<<<SCAN_G, SCAN_B>>>();
    k_scan2<<<1, 128>>>();
    k_scan3<<<SCAN_G, SCAN_B>>>();
    k_scatter<<<eb, 256>>>(ei, ea);

    // encode + layer-0 transform (h, hw0, as0, ad0)
    k_encode_t<<<nb, TPB>>>(x, w_ne1, b_ne1, w_ne2, b_ne2,
                            w_gat, att_src, att_dst);

    // layer 0: aggregate over hw0 -> h; project with w_gat[1] -> hw1/as1/ad1
    k_edge_agg<<<nb, TPB>>>(g_hw0p, g_as0p, g_ad0p, 0, b_gat, ln_g, ln_b);
    k_project<<<GB, 256>>>(g_hp, w_gat + 1 * HIDN * HIDN,
                           att_src + 1 * NHD * DHD, att_dst + 1 * NHD * DHD,
                           nullptr, g_hw1p, g_as1p, g_ad1p, 0);
    // layer 1
    k_edge_agg<<<nb, TPB>>>(g_hw1p, g_as1p, g_ad1p, 1, b_gat, ln_g, ln_b);
    k_project<<<GB, 256>>>(g_hp, w_gat + 2 * HIDN * HIDN,
                           att_src + 2 * NHD * DHD, att_dst + 2 * NHD * DHD,
                           nullptr, g_hw0p, g_as0p, g_ad0p, 0);
    // layer 2 + output projection
    k_edge_agg<<<nb, TPB>>>(g_hw0p, g_as0p, g_ad0p, 2, b_gat, ln_g, ln_b);
    k_project<<<GB, 256>>>(g_hp, w_out, nullptr, nullptr, b_out,
                           out, nullptr, nullptr, 1);
}

// round 13
// speedup vs baseline: 1.6372x; 1.2450x over previous
#include <cuda_runtime.h>

#define NN  100000
#define EE  1200000
#define HIDN 64
#define NHD 4
#define DHD 16
#define NLY 3
#define SCAN_B 1024
#define SCAN_G ((NN + SCAN_B - 1) / SCAN_B)   // 98
#define NPB 16                                 // nodes (warps) per block (edge kernel)
#define TPB (NPB * 32)                         // 512 threads
#define FULLM 0xffffffffu
#define MT 64                                  // GEMM tile: 64 nodes x 64 ch
#define GB ((NN + MT - 1) / MT)                // 1563 tiles

// ---- scratch (static device globals) ----
__device__ float g_h[NN * HIDN];        // node features between layers
__device__ float g_hw0[NN * HIDN];      // transformed features (ping)
__device__ float g_hw1[NN * HIDN];      // transformed features (pong) / enc1 temp
__device__ float g_as0[NN * NHD], g_ad0[NN * NHD];
__device__ float g_as1[NN * NHD], g_ad1[NN * NHD];
__device__ float g_c0[NLY * NHD], g_c1[NLY * NHD];
// CSR by destination: packed (src, ea-bits)
__device__ int   g_deg[NN];
__device__ int   g_rs[NN];
__device__ int   g_cur[NN];
__device__ int2  g_cse[EE];
__device__ int   g_psum[SCAN_G];

// ---------------------------------------------------------------------------
// Edge-attn constants (edge encoder is rank-1 since EIN=1):
// a_e[e,h] = ea[e]*c1[l,h] + c0[l,h]
// ---------------------------------------------------------------------------
__global__ void k_const(const float* __restrict__ w_ee, const float* __restrict__ b_ee,
                        const float* __restrict__ w_eg, const float* __restrict__ att_e)
{
    int l = blockIdx.x, j = threadIdx.x;
    __shared__ float sU[HIDN], sV[HIDN];
    const float* W = w_eg + l * HIDN * HIDN;
    float U = 0.f, V = 0.f;
    for (int k = 0; k < HIDN; k++) {
        float wk = W[k * HIDN + j];
        U += w_ee[k] * wk;
        V += b_ee[k] * wk;
    }
    sU[j] = U; sV[j] = V;
    __syncthreads();
    if (j < NHD) {
        float c1 = 0.f, c0 = 0.f;
        for (int d = 0; d < DHD; d++) {
            float a = att_e[l * HIDN + j * DHD + d];
            c1 += sU[j * DHD + d] * a;
            c0 += sV[j * DHD + d] * a;
        }
        g_c1[l * NHD + j] = c1;
        g_c0[l * NHD + j] = c0;
    }
}

// ---------------------------------------------------------------------------
// CSR build: zero -> count -> scan -> scatter (packed int2)
// ---------------------------------------------------------------------------
__global__ void k_zero()
{
    int i = blockIdx.x * blockDim.x + threadIdx.x;
    if (i < NN) g_deg[i] = 0;
}

__global__ void k_count(const int* __restrict__ ei)
{
    int e = blockIdx.x * blockDim.x + threadIdx.x;
    if (e < EE) atomicAdd(&g_deg[ei[EE + e]], 1);
}

__global__ void k_scan1()
{
    __shared__ int s[SCAN_B];
    int t = threadIdx.x, gid = blockIdx.x * SCAN_B + t;
    int v = (gid < NN) ? g_deg[gid] : 0;
    s[t] = v;
    __syncthreads();
    #pragma unroll
    for (int off = 1; off < SCAN_B; off <<= 1) {
        int u = (t >= off) ? s[t - off] : 0;
        __syncthreads();
        s[t] += u;
        __syncthreads();
    }
    if (gid < NN) g_rs[gid] = s[t] - v;            // exclusive within block
    if (t == SCAN_B - 1) g_psum[blockIdx.x] = s[t];
}

__global__ void k_scan2()
{
    __shared__ int s[SCAN_G];
    int t = threadIdx.x;
    int v = (t < SCAN_G) ? g_psum[t] : 0;
    if (t < SCAN_G) s[t] = v;
    __syncthreads();
    for (int off = 1; off < SCAN_G; off <<= 1) {
        int u = (t >= off && t < SCAN_G) ? s[t - off] : 0;
        __syncthreads();
        if (t < SCAN_G) s[t] += u;
        __syncthreads();
    }
    if (t < SCAN_G) g_psum[t] = s[t] - v;          // exclusive
}

__global__ void k_scan3()
{
    int gid = blockIdx.x * SCAN_B + threadIdx.x;
    if (gid < NN) {
        g_rs[gid] += g_psum[blockIdx.x];
        g_cur[gid] = 0;
    }
}

__global__ void k_scatter(const int* __restrict__ ei, const float* __restrict__ ea)
{
    int e = blockIdx.x * blockDim.x + threadIdx.x;
    if (e >= EE) return;
    int dst = ei[EE + e];
    int pos = g_rs[dst] + atomicAdd(&g_cur[dst], 1);
    g_cse[pos] = make_int2(ei[e], __float_as_int(ea[e]));
}

// ---------------------------------------------------------------------------
// Encoder first linear: t = relu(x @ w1 + b1). Thread per (node, 4 channels).
// ---------------------------------------------------------------------------
__global__ void __launch_bounds__(256)
k_enc1(const float* __restrict__ x,
       const float* __restrict__ w1, const float* __restrict__ b1,
       float* __restrict__ o)
{
    __shared__ float w1s[6][HIDN];
    __shared__ float b1s[HIDN];
    int tid = threadIdx.x;
    for (int i = tid; i < 6 * HIDN; i += 256)      // 384 elems > 256 threads!
        w1s[i / HIDN][i % HIDN] = w1[i];
    if (tid < HIDN) b1s[tid] = b1[tid];
    __syncthreads();

    int gi = blockIdx.x * 256 + tid;
    int n = gi >> 4, cq = gi & 15;
    if (n >= NN) return;

    float xv[6];
    #pragma unroll
    for (int k = 0; k < 6; k++) xv[k] = x[n * 6 + k];

    float4 r = *(const float4*)&b1s[cq * 4];
    #pragma unroll
    for (int k = 0; k < 6; k++) {
        const float* wr = &w1s[k][cq * 4];
        r.x += xv[k] * wr[0];
        r.y += xv[k] * wr[1];
        r.z += xv[k] * wr[2];
        r.w += xv[k] * wr[3];
    }
    r.x = fmaxf(r.x, 0.f); r.y = fmaxf(r.y, 0.f);
    r.z = fmaxf(r.z, 0.f); r.w = fmaxf(r.w, 0.f);
    *(float4*)(o + (size_t)n * HIDN + cq * 4) = r;
}

// ---------------------------------------------------------------------------
// Edge aggregation + node update (NO projection): one warp per dst node.
// Edge loop: lane = slot*8 + t, no shuffles in body. Then
// normalize + bias + ELU + residual + LayerNorm -> g_h in place.
// ---------------------------------------------------------------------------
__global__ void __launch_bounds__(TPB)
k_edge_agg(const float* __restrict__ hw_in,
           const float* __restrict__ as_in, const float* __restrict__ ad_in,
           int l,
           const float* __restrict__ b_gat,
           const float* __restrict__ lng, const float* __restrict__ lnb)
{
    __shared__ float tb[NPB][HIDN];
    int tid = threadIdx.x;
    int warp = tid >> 5, lane = tid & 31;
    int n = blockIdx.x * NPB + warp;
    if (n >= NN) return;

    int t    = lane & 7;                     // channel-slice owner (0..7)
    int slot = lane >> 3;                    // edge slot (0..3)
    int head = t >> 1;                       // head of channels t*8..t*8+7
    float c1h = g_c1[l * NHD + head], c0h = g_c0[l * NHD + head];
    float adh = ad_in[n * NHD + head];
    int base = g_rs[n], dg = g_deg[n];

    const float4* as4 = (const float4*)as_in;

    float acc[8];
    #pragma unroll
    for (int i = 0; i < 8; i++) acc[i] = 0.f;
    float den = 0.f;

    for (int off = 0; off < dg; off += 8) {
        {
            int idx = off + slot;
            bool v = idx < dg;
            int2 se = g_cse[base + (v ? idx : 0)];
            int src = v ? se.x : 0;
            float4 av = as4[src];
            float asv = (head == 0) ? av.x : (head == 1) ? av.y
                      : (head == 2) ? av.z : av.w;
            float s = asv + adh + __int_as_float(se.y) * c1h + c0h;
            s = (s > 0.f) ? s : 0.2f * s;
            float ex = v ? __expf(s) : 0.f;
            den += ex;
            const float4* hp = (const float4*)(hw_in + src * HIDN + t * 8);
            float4 p = hp[0], q = hp[1];
            acc[0] += ex * p.x; acc[1] += ex * p.y;
            acc[2] += ex * p.z; acc[3] += ex * p.w;
            acc[4] += ex * q.x; acc[5] += ex * q.y;
            acc[6] += ex * q.z; acc[7] += ex * q.w;
        }
        {
            int idx = off + 4 + slot;
            bool v = idx < dg;
            int2 se = g_cse[base + (v ? idx : 0)];
            int src = v ? se.x : 0;
            float4 av = as4[src];
            float asv = (head == 0) ? av.x : (head == 1) ? av.y
                      : (head == 2) ? av.z : av.w;
            float s = asv + adh + __int_as_float(se.y) * c1h + c0h;
            s = (s > 0.f) ? s : 0.2f * s;
            float ex = v ? __expf(s) : 0.f;
            den += ex;
            const float4* hp = (const float4*)(hw_in + src * HIDN + t * 8);
            float4 p = hp[0], q = hp[1];
            acc[0] += ex * p.x; acc[1] += ex * p.y;
            acc[2] += ex * p.z; acc[3] += ex * p.w;
            acc[4] += ex * q.x; acc[5] += ex * q.y;
            acc[6] += ex * q.z; acc[7] += ex * q.w;
        }
    }

    // reduce over the 4 edge slots (lanes differing in bits 3,4)
    #pragma unroll
    for (int i = 0; i < 8; i++) {
        acc[i] += __shfl_xor_sync(FULLM, acc[i], 8);
        acc[i] += __shfl_xor_sync(FULLM, acc[i], 16);
    }
    den += __shfl_xor_sync(FULLM, den, 8);
    den += __shfl_xor_sync(FULLM, den, 16);

    // transpose to 2-channels-per-lane layout via per-warp smem buffer
    if (lane < 8) {
        float4* tp = (float4*)&tb[warp][lane * 8];
        tp[0] = make_float4(acc[0], acc[1], acc[2], acc[3]);
        tp[1] = make_float4(acc[4], acc[5], acc[6], acc[7]);
    }
    __syncwarp();
    float num0 = tb[warp][lane];
    float num1 = tb[warp][lane + 32];
    float d0 = __shfl_sync(FULLM, den, 2 * (lane >> 4));
    float d1 = __shfl_sync(FULLM, den, 4 + 2 * (lane >> 4));

    float v0 = num0 / (d0 + 1e-16f) + b_gat[l * HIDN + lane];
    float v1 = num1 / (d1 + 1e-16f) + b_gat[l * HIDN + lane + 32];
    v0 = (v0 > 0.f) ? v0 : expm1f(v0);
    v1 = (v1 > 0.f) ? v1 : expm1f(v1);

    float x0 = g_h[n * HIDN + lane]      + v0;
    float x1 = g_h[n * HIDN + lane + 32] + v1;

    float s = x0 + x1;
    #pragma unroll
    for (int o = 16; o; o >>= 1) s += __shfl_xor_sync(FULLM, s, o);
    float mean = s * (1.f / 64.f);
    float vv = (x0 - mean) * (x0 - mean) + (x1 - mean) * (x1 - mean);
    #pragma unroll
    for (int o = 16; o; o >>= 1) vv += __shfl_xor_sync(FULLM, vv, o);
    float inv = rsqrtf(vv * (1.f / 64.f) + 1e-5f);

    g_h[n * HIDN + lane]      = (x0 - mean) * inv * lng[l * HIDN + lane]      + lnb[l * HIDN + lane];
    g_h[n * HIDN + lane + 32] = (x1 - mean) * inv * lng[l * HIDN + lane + 32] + lnb[l * HIDN + lane + 32];
}

// ---------------------------------------------------------------------------
// Tiled projection GEMM: out[64-node tile][64] = h @ W (+bias).
// 256 threads, per-thread 4x4. h staged transposed hs[k][m]; W staged ws[k][c].
// mode 0: write hw + attention dots (as/ad). mode 1: write out with bias.
// ---------------------------------------------------------------------------
__global__ void __launch_bounds__(256)
k_project(const float* __restrict__ h, const float* __restrict__ W,
          const float* __restrict__ attS, const float* __restrict__ attD,
          const float* __restrict__ bias,
          float* __restrict__ o, float* __restrict__ as_o, float* __restrict__ ad_o,
          int mode)
{
    __shared__ float hs[HIDN][MT + 1];   // [k][m]  (+1: 2-way max on staging stores)
    __shared__ float ws[HIDN][HIDN + 4]; // [k][c]
    __shared__ float sa[HIDN], sd[HIDN];
    int tid = threadIdx.x;
    int m0 = blockIdx.x * MT;

    // stage h transposed: i -> m = i>>4, kq = i&15
    for (int i = tid; i < MT * 16; i += 256) {
        int m = i >> 4, kq = i & 15;
        float4 v = (m0 + m < NN) ? *(const float4*)(h + (size_t)(m0 + m) * HIDN + kq * 4)
                                 : make_float4(0.f, 0.f, 0.f, 0.f);
        hs[kq * 4 + 0][m] = v.x;
        hs[kq * 4 + 1][m] = v.y;
        hs[kq * 4 + 2][m] = v.z;
        hs[kq * 4 + 3][m] = v.w;
    }
    // stage W directly (k-major rows)
    for (int i = tid; i < HIDN * 16; i += 256) {
        int k = i >> 4, cq = i & 15;
        *(float4*)&ws[k][cq * 4] = *(const float4*)(W + k * HIDN + cq * 4);
    }
    if (mode == 0 && tid < HIDN) { sa[tid] = attS[tid]; sd[tid] = attD[tid]; }
    __syncthreads();

    int tx = tid & 15, ty = tid >> 4;        // tx: 4-ch group, ty: 4-node group
    float acc[4][4];
    #pragma unroll
    for (int i = 0; i < 4; i++)
        #pragma unroll
        for (int j = 0; j < 4; j++) acc[i][j] = 0.f;

    #pragma unroll
    for (int k = 0; k < HIDN; k++) {
        float4 hv = make_float4(hs[k][ty * 4], hs[k][ty * 4 + 1],
                                hs[k][ty * 4 + 2], hs[k][ty * 4 + 3]);
        float4 wv = *(float4*)&ws[k][tx * 4];
        acc[0][0] += hv.x * wv.x; acc[0][1] += hv.x * wv.y;
        acc[0][2] += hv.x * wv.z; acc[0][3] += hv.x * wv.w;
        acc[1][0] += hv.y * wv.x; acc[1][1] += hv.y * wv.y;
        acc[1][2] += hv.y * wv.z; acc[1][3] += hv.y * wv.w;
        acc[2][0] += hv.z * wv.x; acc[2][1] += hv.z * wv.y;
        acc[2][2] += hv.z * wv.z; acc[2][3] += hv.z * wv.w;
        acc[3][0] += hv.w * wv.x; acc[3][1] += hv.w * wv.y;
        acc[3][2] += hv.w * wv.z; acc[3][3] += hv.w * wv.w;
    }

    if (mode == 1) {
        float4 bv = *(const float4*)(bias + tx * 4);
        #pragma unroll
        for (int mi = 0; mi < 4; mi++) {
            int n = m0 + ty * 4 + mi;
            if (n < NN)
                *(float4*)(o + (size_t)n * HIDN + tx * 4) =
                    make_float4(acc[mi][0] + bv.x, acc[mi][1] + bv.y,
                                acc[mi][2] + bv.z, acc[mi][3] + bv.w);
        }
        return;
    }

    // mode 0: store hw + attention dots
    #pragma unroll
    for (int mi = 0; mi < 4; mi++) {
        int n = m0 + ty * 4 + mi;
        if (n < NN)
            *(float4*)(o + (size_t)n * HIDN + tx * 4) =
                make_float4(acc[mi][0], acc[mi][1], acc[mi][2], acc[mi][3]);
    }
    // dots: channels tx*4..tx*4+3 all lie in head tx>>2
    float4 sav = *(float4*)&sa[tx * 4];
    float4 sdv = *(float4*)&sd[tx * 4];
    #pragma unroll
    for (int mi = 0; mi < 4; mi++) {
        float ps = acc[mi][0] * sav.x + acc[mi][1] * sav.y
                 + acc[mi][2] * sav.z + acc[mi][3] * sav.w;
        float pd = acc[mi][0] * sdv.x + acc[mi][1] * sdv.y
                 + acc[mi][2] * sdv.z + acc[mi][3] * sdv.w;
        // reduce over the 4 tx's of this head (lane bits 0,1)
        ps += __shfl_xor_sync(FULLM, ps, 1);
        ps += __shfl_xor_sync(FULLM, ps, 2);
        pd += __shfl_xor_sync(FULLM, pd, 1);
        pd += __shfl_xor_sync(FULLM, pd, 2);
        int n = m0 + ty * 4 + mi;
        if ((tx & 3) == 0 && n < NN) {
            as_o[n * NHD + (tx >> 2)] = ps;
            ad_o[n * NHD + (tx >> 2)] = pd;
        }
    }
}

// ---------------------------------------------------------------------------
extern "C" void kernel_launch(void* const* d_in, const int* in_sizes, int n_in,
                              void* d_out, int out_size)
{
    const float* x        = (const float*)d_in[0];
    const int*   ei       = (const int*)d_in[1];     // int64 in ref -> int32 on device
    const float* ea       = (const float*)d_in[2];
    const float* w_ne1    = (const float*)d_in[3];
    const float* b_ne1    = (const float*)d_in[4];
    const float* w_ne2    = (const float*)d_in[5];
    const float* b_ne2    = (const float*)d_in[6];
    const float* w_ee     = (const float*)d_in[7];
    const float* b_ee     = (const float*)d_in[8];
    const float* w_gat    = (const float*)d_in[9];
    const float* w_eg     = (const float*)d_in[10];
    const float* att_src  = (const float*)d_in[11];
    const float* att_dst  = (const float*)d_in[12];
    const float* att_edge = (const float*)d_in[13];
    const float* b_gat    = (const float*)d_in[14];
    const float* ln_g     = (const float*)d_in[15];
    const float* ln_b     = (const float*)d_in[16];
    const float* w_out    = (const float*)d_in[17];
    const float* b_out    = (const float*)d_in[18];
    float*       out      = (float*)d_out;

    int nb = (NN + NPB - 1) / NPB;
    int eb = (EE + 255) / 256;

    float* g_hp;    cudaGetSymbolAddress((void**)&g_hp,   g_h);
    float* g_hw0p;  cudaGetSymbolAddress((void**)&g_hw0p, g_hw0);
    float* g_hw1p;  cudaGetSymbolAddress((void**)&g_hw1p, g_hw1);
    float* g_as0p;  cudaGetSymbolAddress((void**)&g_as0p, g_as0);
    float* g_ad0p;  cudaGetSymbolAddress((void**)&g_ad0p, g_ad0);
    float* g_as1p;  cudaGetSymbolAddress((void**)&g_as1p, g_as1);
    float* g_ad1p;  cudaGetSymbolAddress((void**)&g_ad1p, g_ad1);

    k_const<<<NLY, HIDN>>>(w_ee, b_ee, w_eg, att_edge);

    // CSR build (amortized over 3 layers)
    k_zero<<<(NN + 255) / 256, 256>>>();
    k_count<<<eb, 256>>>(ei);
    k_scan1<<<SCAN_G, SCAN_B>>>();
    k_scan2<<<1, 128>>>();
    k_scan3<<<SCAN_G, SCAN_B>>>();
    k_scatter<<<eb, 256>>>(ei, ea);

    // encoder: enc1 -> hw1 (temp); project w_ne2 -> h; project w_gat[0] -> hw0/as0/ad0
    k_enc1<<<(NN * 16 + 255) / 256, 256>>>(x, w_ne1, b_ne1, g_hw1p);
    k_project<<<GB, 256>>>(g_hw1p, w_ne2, nullptr, nullptr, b_ne2,
                           g_hp, nullptr, nullptr, 1);
    k_project<<<GB, 256>>>(g_hp, w_gat,
                           att_src, att_dst,
                           nullptr, g_hw0p, g_as0p, g_ad0p, 0);

    // layer 0: aggregate over hw0 -> h; project with w_gat[1] -> hw1/as1/ad1
    k_edge_agg<<<nb, TPB>>>(g_hw0p, g_as0p, g_ad0p, 0, b_gat, ln_g, ln_b);
    k_project<<<GB, 256>>>(g_hp, w_gat + 1 * HIDN * HIDN,
                           att_src + 1 * NHD * DHD, att_dst + 1 * NHD * DHD,
                           nullptr, g_hw1p, g_as1p, g_ad1p, 0);
    // layer 1
    k_edge_agg<<<nb, TPB>>>(g_hw1p, g_as1p, g_ad1p, 1, b_gat, ln_g, ln_b);
    k_project<<<GB, 256>>>(g_hp, w_gat + 2 * HIDN * HIDN,
                           att_src + 2 * NHD * DHD, att_dst + 2 * NHD * DHD,
                           nullptr, g_hw0p, g_as0p, g_ad0p, 0);
    // layer 2 + output projection
    k_edge_agg<<<nb, TPB>>>(g_hw0p, g_as0p, g_ad0p, 2, b_gat, ln_g, ln_b);
    k_project<<<GB, 256>>>(g_hp, w_out, nullptr, nullptr, b_out,
                           out, nullptr, nullptr, 1);
}

// round 14
// speedup vs baseline: 1.7091x; 1.0439x over previous
#include <cuda_runtime.h>

#define NN  100000
#define EE  1200000
#define HIDN 64
#define NHD 4
#define DHD 16
#define NLY 3
#define SCAN_B 1024
#define SCAN_G ((NN + SCAN_B - 1) / SCAN_B)   // 98
#define NPB 16                                 // nodes (warps) per block (edge kernel)
#define TPB (NPB * 32)                         // 512 threads
#define FULLM 0xffffffffu
#define MT 64                                  // GEMM tile: 64 nodes x 64 ch
#define GB ((NN + MT - 1) / MT)                // 1563 tiles

// packed f32x2 helpers (bit-identical to scalar fma.rn per lane)
#define PACKF(out, f) \
    asm("mov.b64 %0, {%1, %2};" : "=l"(out) : "r"(__float_as_uint(f)), "r"(__float_as_uint(f)))
#define UNPACKF(lo, hi, in) do { unsigned _ulo, _uhi; \
    asm("mov.b64 {%0, %1}, %2;" : "=r"(_ulo), "=r"(_uhi) : "l"(in)); \
    lo = __uint_as_float(_ulo); hi = __uint_as_float(_uhi); } while (0)
#define FMA2(d, a, b, c) \
    asm("fma.rn.f32x2 %0, %1, %2, %3;" : "=l"(d) : "l"(a), "l"(b), "l"(c))
#define ADD2(d, a, b) \
    asm("add.rn.f32x2 %0, %1, %2;" : "=l"(d) : "l"(a), "l"(b))

// ---- scratch (static device globals) ----
__device__ float g_h[NN * HIDN];        // node features between layers
__device__ float g_hw0[NN * HIDN];      // transformed features (ping)
__device__ float g_hw1[NN * HIDN];      // transformed features (pong)
__device__ float g_as0[NN * NHD], g_ad0[NN * NHD];
__device__ float g_as1[NN * NHD], g_ad1[NN * NHD];
__device__ float g_c0[NLY * NHD], g_c1[NLY * NHD];
// CSR by destination: packed (src, ea-bits)
__device__ int   g_deg[NN];
__device__ int   g_rs[NN];
__device__ int   g_cur[NN];
__device__ int2  g_cse[EE];
__device__ int   g_psum[SCAN_G];

// ---------------------------------------------------------------------------
// Edge-attn constants (edge encoder is rank-1 since EIN=1):
// a_e[e,h] = ea[e]*c1[l,h] + c0[l,h]
// ---------------------------------------------------------------------------
__global__ void k_const(const float* __restrict__ w_ee, const float* __restrict__ b_ee,
                        const float* __restrict__ w_eg, const float* __restrict__ att_e)
{
    int l = blockIdx.x, j = threadIdx.x;
    __shared__ float sU[HIDN], sV[HIDN];
    const float* W = w_eg + l * HIDN * HIDN;
    float U = 0.f, V = 0.f;
    for (int k = 0; k < HIDN; k++) {
        float wk = W[k * HIDN + j];
        U += w_ee[k] * wk;
        V += b_ee[k] * wk;
    }
    sU[j] = U; sV[j] = V;
    __syncthreads();
    if (j < NHD) {
        float c1 = 0.f, c0 = 0.f;
        for (int d = 0; d < DHD; d++) {
            float a = att_e[l * HIDN + j * DHD + d];
            c1 += sU[j * DHD + d] * a;
            c0 += sV[j * DHD + d] * a;
        }
        g_c1[l * NHD + j] = c1;
        g_c0[l * NHD + j] = c0;
    }
}

// ---------------------------------------------------------------------------
// CSR build: zero -> count -> scan -> scatter (packed int2)
// ---------------------------------------------------------------------------
__global__ void k_zero()
{
    int i = blockIdx.x * blockDim.x + threadIdx.x;
    if (i < NN) g_deg[i] = 0;
}

__global__ void k_count(const int* __restrict__ ei)
{
    int e = blockIdx.x * blockDim.x + threadIdx.x;
    if (e < EE) atomicAdd(&g_deg[ei[EE + e]], 1);
}

__global__ void k_scan1()
{
    __shared__ int s[SCAN_B];
    int t = threadIdx.x, gid = blockIdx.x * SCAN_B + t;
    int v = (gid < NN) ? g_deg[gid] : 0;
    s[t] = v;
    __syncthreads();
    #pragma unroll
    for (int off = 1; off < SCAN_B; off <<= 1) {
        int u = (t >= off) ? s[t - off] : 0;
        __syncthreads();
        s[t] += u;
        __syncthreads();
    }
    if (gid < NN) g_rs[gid] = s[t] - v;            // exclusive within block
    if (t == SCAN_B - 1) g_psum[blockIdx.x] = s[t];
}

__global__ void k_scan2()
{
    __shared__ int s[SCAN_G];
    int t = threadIdx.x;
    int v = (t < SCAN_G) ? g_psum[t] : 0;
    if (t < SCAN_G) s[t] = v;
    __syncthreads();
    for (int off = 1; off < SCAN_G; off <<= 1) {
        int u = (t >= off && t < SCAN_G) ? s[t - off] : 0;
        __syncthreads();
        if (t < SCAN_G) s[t] += u;
        __syncthreads();
    }
    if (t < SCAN_G) g_psum[t] = s[t] - v;          // exclusive
}

__global__ void k_scan3()
{
    int gid = blockIdx.x * SCAN_B + threadIdx.x;
    if (gid < NN) {
        g_rs[gid] += g_psum[blockIdx.x];
        g_cur[gid] = 0;
    }
}

__global__ void k_scatter(const int* __restrict__ ei, const float* __restrict__ ea)
{
    int e = blockIdx.x * blockDim.x + threadIdx.x;
    if (e >= EE) return;
    int dst = ei[EE + e];
    int pos = g_rs[dst] + atomicAdd(&g_cur[dst], 1);
    g_cse[pos] = make_int2(ei[e], __float_as_int(ea[e]));
}

// ---------------------------------------------------------------------------
// Edge aggregation + node update (NO projection): one warp per dst node.
// Edge loop: lane = slot*8 + t, no shuffles in body, f32x2 accumulate. Then
// normalize + bias + ELU + residual + LayerNorm -> g_h in place.
// ---------------------------------------------------------------------------
__global__ void __launch_bounds__(TPB)
k_edge_agg(const float* __restrict__ hw_in,
           const float* __restrict__ as_in, const float* __restrict__ ad_in,
           int l,
           const float* __restrict__ b_gat,
           const float* __restrict__ lng, const float* __restrict__ lnb)
{
    __shared__ float tb[NPB][HIDN];
    int tid = threadIdx.x;
    int warp = tid >> 5, lane = tid & 31;
    int n = blockIdx.x * NPB + warp;
    if (n >= NN) return;

    int t    = lane & 7;                     // channel-slice owner (0..7)
    int slot = lane >> 3;                    // edge slot (0..3)
    int head = t >> 1;                       // head of channels t*8..t*8+7
    float c1h = g_c1[l * NHD + head], c0h = g_c0[l * NHD + head];
    float adh = ad_in[n * NHD + head];
    int base = g_rs[n], dg = g_deg[n];

    const float4* as4 = (const float4*)as_in;

    unsigned long long acc2[4] = {0ull, 0ull, 0ull, 0ull};
    float den = 0.f;

    for (int off = 0; off < dg; off += 8) {
        {
            int idx = off + slot;
            bool v = idx < dg;
            int2 se = g_cse[base + (v ? idx : 0)];
            int src = v ? se.x : 0;
            float4 av = as4[src];
            float asv = (head == 0) ? av.x : (head == 1) ? av.y
                      : (head == 2) ? av.z : av.w;
            float s = asv + adh + __int_as_float(se.y) * c1h + c0h;
            s = (s > 0.f) ? s : 0.2f * s;
            float ex = v ? __expf(s) : 0.f;
            den += ex;
            unsigned long long exp2v; PACKF(exp2v, ex);
            const ulonglong2* hp = (const ulonglong2*)(hw_in + src * HIDN + t * 8);
            ulonglong2 P = hp[0], Q = hp[1];
            FMA2(acc2[0], exp2v, P.x, acc2[0]);
            FMA2(acc2[1], exp2v, P.y, acc2[1]);
            FMA2(acc2[2], exp2v, Q.x, acc2[2]);
            FMA2(acc2[3], exp2v, Q.y, acc2[3]);
        }
        {
            int idx = off + 4 + slot;
            bool v = idx < dg;
            int2 se = g_cse[base + (v ? idx : 0)];
            int src = v ? se.x : 0;
            float4 av = as4[src];
            float asv = (head == 0) ? av.x : (head == 1) ? av.y
                      : (head == 2) ? av.z : av.w;
            float s = asv + adh + __int_as_float(se.y) * c1h + c0h;
            s = (s > 0.f) ? s : 0.2f * s;
            float ex = v ? __expf(s) : 0.f;
            den += ex;
            unsigned long long exp2v; PACKF(exp2v, ex);
            const ulonglong2* hp = (const ulonglong2*)(hw_in + src * HIDN + t * 8);
            ulonglong2 P = hp[0], Q = hp[1];
            FMA2(acc2[0], exp2v, P.x, acc2[0]);
            FMA2(acc2[1], exp2v, P.y, acc2[1]);
            FMA2(acc2[2], exp2v, Q.x, acc2[2]);
            FMA2(acc2[3], exp2v, Q.y, acc2[3]);
        }
    }

    // reduce over the 4 edge slots (lanes differing in bits 3,4)
    #pragma unroll
    for (int i = 0; i < 4; i++) {
        unsigned long long o8  = __shfl_xor_sync(FULLM, acc2[i], 8);
        ADD2(acc2[i], acc2[i], o8);
        unsigned long long o16 = __shfl_xor_sync(FULLM, acc2[i], 16);
        ADD2(acc2[i], acc2[i], o16);
    }
    den += __shfl_xor_sync(FULLM, den, 8);
    den += __shfl_xor_sync(FULLM, den, 16);

    // transpose to 2-channels-per-lane layout via per-warp smem buffer
    if (lane < 8) {
        float f0, f1, f2, f3, f4, f5, f6, f7;
        UNPACKF(f0, f1, acc2[0]);
        UNPACKF(f2, f3, acc2[1]);
        UNPACKF(f4, f5, acc2[2]);
        UNPACKF(f6, f7, acc2[3]);
        float4* tp = (float4*)&tb[warp][lane * 8];
        tp[0] = make_float4(f0, f1, f2, f3);
        tp[1] = make_float4(f4, f5, f6, f7);
    }
    __syncwarp();
    float num0 = tb[warp][lane];
    float num1 = tb[warp][lane + 32];
    float d0 = __shfl_sync(FULLM, den, 2 * (lane >> 4));
    float d1 = __shfl_sync(FULLM, den, 4 + 2 * (lane >> 4));

    float v0 = num0 / (d0 + 1e-16f) + b_gat[l * HIDN + lane];
    float v1 = num1 / (d1 + 1e-16f) + b_gat[l * HIDN + lane + 32];
    v0 = (v0 > 0.f) ? v0 : expm1f(v0);
    v1 = (v1 > 0.f) ? v1 : expm1f(v1);

    float x0 = g_h[n * HIDN + lane]      + v0;
    float x1 = g_h[n * HIDN + lane + 32] + v1;

    float s = x0 + x1;
    #pragma unroll
    for (int o = 16; o; o >>= 1) s += __shfl_xor_sync(FULLM, s, o);
    float mean = s * (1.f / 64.f);
    float vv = (x0 - mean) * (x0 - mean) + (x1 - mean) * (x1 - mean);
    #pragma unroll
    for (int o = 16; o; o >>= 1) vv += __shfl_xor_sync(FULLM, vv, o);
    float inv = rsqrtf(vv * (1.f / 64.f) + 1e-5f);

    g_h[n * HIDN + lane]      = (x0 - mean) * inv * lng[l * HIDN + lane]      + lnb[l * HIDN + lane];
    g_h[n * HIDN + lane + 32] = (x1 - mean) * inv * lng[l * HIDN + lane + 32] + lnb[l * HIDN + lane + 32];
}

// ---------------------------------------------------------------------------
// Tiled projection GEMM: out[64-node tile][64] = h @ W (+bias).
// 256 threads, per-thread 4x4, k blocked by 4, f32x2 packed FMA.
// hs kept [m][k] (vector LDS both sides).
// mode 0: write hw + attention dots (as/ad).
// mode 1: write o = h@W + bias.
// mode 2: like mode 1 but h is computed on the fly: relu(x@w1 + b1), x=[N,6].
// ---------------------------------------------------------------------------
__global__ void __launch_bounds__(256)
k_project(const float* __restrict__ h, const float* __restrict__ W,
          const float* __restrict__ attS, const float* __restrict__ attD,
          const float* __restrict__ bias,
          const float* __restrict__ w1, const float* __restrict__ b1,
          float* __restrict__ o, float* __restrict__ as_o, float* __restrict__ ad_o,
          int mode)
{
    __shared__ float hs[MT][HIDN + 4];   // [m][k], rows 272B (16B aligned)
    __shared__ float ws[HIDN][HIDN + 4]; // [k][c]
    __shared__ float sa[HIDN], sd[HIDN];
    __shared__ float w1s[6][HIDN];
    __shared__ float b1s[HIDN];
    int tid = threadIdx.x;
    int m0 = blockIdx.x * MT;

    if (mode == 2) {
        for (int i = tid; i < 6 * HIDN; i += 256)
            w1s[i / HIDN][i % HIDN] = w1[i];
        if (tid < HIDN) b1s[tid] = b1[tid];
    }
    // stage W (k-major rows)
    for (int i = tid; i < HIDN * 16; i += 256) {
        int k = i >> 4, cq = i & 15;
        *(float4*)&ws[k][cq * 4] = *(const float4*)(W + k * HIDN + cq * 4);
    }
    if (mode == 0 && tid < HIDN) { sa[tid] = attS[tid]; sd[tid] = attD[tid]; }
    if (mode == 2) __syncthreads();      // w1s ready before hs compute

    // stage h [m][k] (vectorized)
    for (int i = tid; i < MT * 16; i += 256) {
        int m = i >> 4, kq = i & 15;
        float4 v;
        if (mode == 2) {
            // compute relu(x @ w1 + b1) channels kq*4..kq*4+3 for node m0+m
            v = make_float4(0.f, 0.f, 0.f, 0.f);
            if (m0 + m < NN) {
                float xv[6];
                #pragma unroll
                for (int k = 0; k < 6; k++) xv[k] = h[(size_t)(m0 + m) * 6 + k];
                v = *(const float4*)&b1s[kq * 4];
                #pragma unroll
                for (int k = 0; k < 6; k++) {
                    const float* wr = &w1s[k][kq * 4];
                    v.x += xv[k] * wr[0];
                    v.y += xv[k] * wr[1];
                    v.z += xv[k] * wr[2];
                    v.w += xv[k] * wr[3];
                }
                v.x = fmaxf(v.x, 0.f); v.y = fmaxf(v.y, 0.f);
                v.z = fmaxf(v.z, 0.f); v.w = fmaxf(v.w, 0.f);
            }
        } else {
            v = (m0 + m < NN) ? *(const float4*)(h + (size_t)(m0 + m) * HIDN + kq * 4)
                              : make_float4(0.f, 0.f, 0.f, 0.f);
        }
        *(float4*)&hs[m][kq * 4] = v;
    }
    __syncthreads();

    int tx = tid & 15, ty = tid >> 4;        // tx: 4-ch group, ty: 4-node group
    unsigned long long a2[4][2];
    #pragma unroll
    for (int i = 0; i < 4; i++) { a2[i][0] = 0ull; a2[i][1] = 0ull; }

    #pragma unroll
    for (int k4 = 0; k4 < 16; k4++) {
        float4 hv0 = *(const float4*)&hs[ty * 4 + 0][k4 * 4];
        float4 hv1 = *(const float4*)&hs[ty * 4 + 1][k4 * 4];
        float4 hv2 = *(const float4*)&hs[ty * 4 + 2][k4 * 4];
        float4 hv3 = *(const float4*)&hs[ty * 4 + 3][k4 * 4];
        float h0[4] = {hv0.x, hv0.y, hv0.z, hv0.w};
        float h1[4] = {hv1.x, hv1.y, hv1.z, hv1.w};
        float h2[4] = {hv2.x, hv2.y, hv2.z, hv2.w};
        float h3[4] = {hv3.x, hv3.y, hv3.z, hv3.w};
        #pragma unroll
        for (int kk = 0; kk < 4; kk++) {
            ulonglong2 w = *(const ulonglong2*)&ws[k4 * 4 + kk][tx * 4];
            unsigned long long p0, p1, p2, p3;
            PACKF(p0, h0[kk]); PACKF(p1, h1[kk]);
            PACKF(p2, h2[kk]); PACKF(p3, h3[kk]);
            FMA2(a2[0][0], p0, w.x, a2[0][0]); FMA2(a2[0][1], p0, w.y, a2[0][1]);
            FMA2(a2[1][0], p1, w.x, a2[1][0]); FMA2(a2[1][1], p1, w.y, a2[1][1]);
            FMA2(a2[2][0], p2, w.x, a2[2][0]); FMA2(a2[2][1], p2, w.y, a2[2][1]);
            FMA2(a2[3][0], p3, w.x, a2[3][0]); FMA2(a2[3][1], p3, w.y, a2[3][1]);
        }
    }

    float acc[4][4];
    #pragma unroll
    for (int mi = 0; mi < 4; mi++) {
        UNPACKF(acc[mi][0], acc[mi][1], a2[mi][0]);
        UNPACKF(acc[mi][2], acc[mi][3], a2[mi][1]);
    }

    if (mode != 0) {
        float4 bv = *(const float4*)(bias + tx * 4);
        #pragma unroll
        for (int mi = 0; mi < 4; mi++) {
            int n = m0 + ty * 4 + mi;
            if (n < NN)
                *(float4*)(o + (size_t)n * HIDN + tx * 4) =
                    make_float4(acc[mi][0] + bv.x, acc[mi][1] + bv.y,
                                acc[mi][2] + bv.z, acc[mi][3] + bv.w);
        }
        return;
    }

    // mode 0: store hw + attention dots
    #pragma unroll
    for (int mi = 0; mi < 4; mi++) {
        int n = m0 + ty * 4 + mi;
        if (n < NN)
            *(float4*)(o + (size_t)n * HIDN + tx * 4) =
                make_float4(acc[mi][0], acc[mi][1], acc[mi][2], acc[mi][3]);
    }
    // dots: channels tx*4..tx*4+3 all lie in head tx>>2
    float4 sav = *(float4*)&sa[tx * 4];
    float4 sdv = *(float4*)&sd[tx * 4];
    #pragma unroll
    for (int mi = 0; mi < 4; mi++) {
        float ps = acc[mi][0] * sav.x + acc[mi][1] * sav.y
                 + acc[mi][2] * sav.z + acc[mi][3] * sav.w;
        float pd = acc[mi][0] * sdv.x + acc[mi][1] * sdv.y
                 + acc[mi][2] * sdv.z + acc[mi][3] * sdv.w;
        // reduce over the 4 tx's of this head (lane bits 0,1)
        ps += __shfl_xor_sync(FULLM, ps, 1);
        ps += __shfl_xor_sync(FULLM, ps, 2);
        pd += __shfl_xor_sync(FULLM, pd, 1);
        pd += __shfl_xor_sync(FULLM, pd, 2);
        int n = m0 + ty * 4 + mi;
        if ((tx & 3) == 0 && n < NN) {
            as_o[n * NHD + (tx >> 2)] = ps;
            ad_o[n * NHD + (tx >> 2)] = pd;
        }
    }
}

// ---------------------------------------------------------------------------
extern "C" void kernel_launch(void* const* d_in, const int* in_sizes, int n_in,
                              void* d_out, int out_size)
{
    const float* x        = (const float*)d_in[0];
    const int*   ei       = (const int*)d_in[1];     // int64 in ref -> int32 on device
    const float* ea       = (const float*)d_in[2];
    const float* w_ne1    = (const float*)d_in[3];
    const float* b_ne1    = (const float*)d_in[4];
    const float* w_ne2    = (const float*)d_in[5];
    const float* b_ne2    = (const float*)d_in[6];
    const float* w_ee     = (const float*)d_in[7];
    const float* b_ee     = (const float*)d_in[8];
    const float* w_gat    = (const float*)d_in[9];
    const float* w_eg     = (const float*)d_in[10];
    const float* att_src  = (const float*)d_in[11];
    const float* att_dst  = (const float*)d_in[12];
    const float* att_edge = (const float*)d_in[13];
    const float* b_gat    = (const float*)d_in[14];
    const float* ln_g     = (const float*)d_in[15];
    const float* ln_b     = (const float*)d_in[16];
    const float* w_out    = (const float*)d_in[17];
    const float* b_out    = (const float*)d_in[18];
    float*       out      = (float*)d_out;

    int nb = (NN + NPB - 1) / NPB;
    int eb = (EE + 255) / 256;

    float* g_hp;    cudaGetSymbolAddress((void**)&g_hp,   g_h);
    float* g_hw0p;  cudaGetSymbolAddress((void**)&g_hw0p, g_hw0);
    float* g_hw1p;  cudaGetSymbolAddress((void**)&g_hw1p, g_hw1);
    float* g_as0p;  cudaGetSymbolAddress((void**)&g_as0p, g_as0);
    float* g_ad0p;  cudaGetSymbolAddress((void**)&g_ad0p, g_ad0);
    float* g_as1p;  cudaGetSymbolAddress((void**)&g_as1p, g_as1);
    float* g_ad1p;  cudaGetSymbolAddress((void**)&g_ad1p, g_ad1);

    k_const<<<NLY, HIDN>>>(w_ee, b_ee, w_eg, att_edge);

    // CSR build (amortized over 3 layers)
    k_zero<<<(NN + 255) / 256, 256>>>();
    k_count<<<eb, 256>>>(ei);
    k_scan1<<<SCAN_G, SCAN_B>>>();
    k_scan2<<<1, 128>>>();
    k_scan3<<<SCAN_G, SCAN_B>>>();
    k_scatter<<<eb, 256>>>(ei, ea);

    // encoder fused: h = relu(x w1 + b1) w2 + b2   (mode 2)
    k_project<<<GB, 256>>>(x, w_ne2, nullptr, nullptr, b_ne2, w_ne1, b_ne1,
                           g_hp, nullptr, nullptr, 2);
    // layer-0 transform
    k_project<<<GB, 256>>>(g_hp, w_gat, att_src, att_dst, nullptr, nullptr, nullptr,
                           g_hw0p, g_as0p, g_ad0p, 0);

    // layer 0
    k_edge_agg<<<nb, TPB>>>(g_hw0p, g_as0p, g_ad0p, 0, b_gat, ln_g, ln_b);
    k_project<<<GB, 256>>>(g_hp, w_gat + 1 * HIDN * HIDN,
                           att_src + 1 * NHD * DHD, att_dst + 1 * NHD * DHD,
                           nullptr, nullptr, nullptr,
                           g_hw1p, g_as1p, g_ad1p, 0);
    // layer 1
    k_edge_agg<<<nb, TPB>>>(g_hw1p, g_as1p, g_ad1p, 1, b_gat, ln_g, ln_b);
    k_project<<<GB, 256>>>(g_hp, w_gat + 2 * HIDN * HIDN,
                           att_src + 2 * NHD * DHD, att_dst + 2 * NHD * DHD,
                           nullptr, nullptr, nullptr,
                           g_hw0p, g_as0p, g_ad0p, 0);
    // layer 2 + output projection
    k_edge_agg<<<nb, TPB>>>(g_hw0p, g_as0p, g_ad0p, 2, b_gat, ln_g, ln_b);
    k_project<<<GB, 256>>>(g_hp, w_out, nullptr, nullptr, b_out, nullptr, nullptr,
                           out, nullptr, nullptr, 1);
}